// round 3
// baseline (speedup 1.0000x reference)
#include <cuda_runtime.h>

// Problem-shape upper bounds (N=100000, E=1600000 for this dataset).
#define NMAX 100000
#define EMAX 1600000

// ---------------- scratch (static device globals; 16B-aligned for LDG.128) --
__device__ __align__(16) float g_h1[(size_t)NMAX * 128];    // layer1 features
__device__ __align__(16) float g_out1[(size_t)NMAX * 128];  // relu(gat1 + b1)
__device__ __align__(16) float g_h2[(size_t)NMAX * 128];    // layer2 features
__device__ float4 g_asrc1[NMAX];
__device__ float4 g_adst1[NMAX];
__device__ float4 g_asrc2[NMAX];
__device__ float4 g_adst2[NMAX];
__device__ int    g_count[NMAX];
__device__ int    g_rowptr[NMAX + 1];
__device__ int    g_cursor[NMAX];
__device__ int    g_colsrc[EMAX + NMAX];  // CSR column (src) indices, dst-sorted

__device__ __forceinline__ float warpsum(float v) {
  v += __shfl_xor_sync(0xffffffffu, v, 16);
  v += __shfl_xor_sync(0xffffffffu, v, 8);
  v += __shfl_xor_sync(0xffffffffu, v, 4);
  v += __shfl_xor_sync(0xffffffffu, v, 2);
  v += __shfl_xor_sync(0xffffffffu, v, 1);
  return v;
}

// ---------------- CSR build --------------------------------------------------
__global__ void init_count_kernel(int N) {
  int i = blockIdx.x * blockDim.x + threadIdx.x;
  if (i < N) g_count[i] = 1;  // 1 accounts for the self-loop
}

__global__ void hist_kernel(const int* __restrict__ dstv, int E) {
  int i = blockIdx.x * blockDim.x + threadIdx.x;
  if (i < E) atomicAdd(&g_count[dstv[i]], 1);
}

// Single-block exclusive scan of g_count -> g_rowptr (+ cursor copy).
__global__ void scan_kernel(int N) {
  __shared__ int s[1024];
  int t = threadIdx.x;
  int CH = (N + 1023) >> 10;
  int b0 = t * CH;
  int b1 = b0 + CH; if (b1 > N) b1 = N;
  int sum = 0;
  for (int i = b0; i < b1; ++i) sum += g_count[i];
  s[t] = sum;
  __syncthreads();
  for (int off = 1; off < 1024; off <<= 1) {
    int v = (t >= off) ? s[t - off] : 0;
    __syncthreads();
    s[t] += v;
    __syncthreads();
  }
  int run = s[t] - sum;  // exclusive prefix
  for (int i = b0; i < b1; ++i) {
    g_rowptr[i] = run;
    g_cursor[i] = run;
    run += g_count[i];
  }
  if (t == 1023) g_rowptr[N] = s[1023];
}

__global__ void scatter_kernel(const int* __restrict__ srcv,
                               const int* __restrict__ dstv, int E, int N) {
  int i = blockIdx.x * blockDim.x + threadIdx.x;
  if (i < E) {
    int p = atomicAdd(&g_cursor[dstv[i]], 1);
    g_colsrc[p] = srcv[i];
  } else if (i < E + N) {
    int n = i - E;  // self loop
    int p = atomicAdd(&g_cursor[n], 1);
    g_colsrc[p] = n;
  }
}

// ---------------- layer-1 GEMM: h1 = x[N,8] @ W1[8,128]  (+ per-head a) -----
__global__ void gemm1_kernel(const float* __restrict__ x,
                             const float* __restrict__ W1,
                             const float* __restrict__ att_s,
                             const float* __restrict__ att_d, int N) {
  __shared__ float sW[8 * 128];
  __shared__ float sAs[128], sAd[128];
  int tid = threadIdx.x;  // 128 threads; tid = output column = head*32+ch
  for (int i = tid; i < 1024; i += 128) sW[i] = W1[i];
  sAs[tid] = att_s[tid];
  sAd[tid] = att_d[tid];
  __syncthreads();
  int head = tid >> 5, lane = tid & 31;
  int base = blockIdx.x * 8;
  for (int m = 0; m < 8; ++m) {
    int n = base + m;
    if (n >= N) break;  // uniform across block
    float acc = 0.f;
#pragma unroll
    for (int k = 0; k < 8; ++k) acc = fmaf(__ldg(&x[n * 8 + k]), sW[k * 128 + tid], acc);
    g_h1[(size_t)n * 128 + tid] = acc;
    float vs = warpsum(acc * sAs[tid]);
    float vd = warpsum(acc * sAd[tid]);
    if (lane == 0) {
      float* ps = (float*)&g_asrc1[n];
      float* pd = (float*)&g_adst1[n];
      ps[head] = vs;
      pd[head] = vd;
    }
  }
}

// ---------------- layer-2 GEMM: h2 = out1[N,128] @ W2[128,128] (+ a) --------
// K-chunked; static smem only (16KB W-chunk + 8KB input + 1KB att = 25KB).
__global__ void gemm2_kernel(const float* __restrict__ W2,
                             const float* __restrict__ att_s,
                             const float* __restrict__ att_d, int N) {
  __shared__ float sW[32 * 128];   // one 32-row K chunk of W2
  __shared__ float sIn[16 * 128];  // 16 input rows
  __shared__ float sAs[128], sAd[128];
  int tid = threadIdx.x;  // 128
  sAs[tid] = att_s[tid];
  sAd[tid] = att_d[tid];
  int base = blockIdx.x * 16;
  for (int i = tid; i < 2048; i += 128) {
    int r = base + (i >> 7);
    sIn[i] = (r < N) ? g_out1[(size_t)r * 128 + (i & 127)] : 0.f;
  }
  float acc[16];
#pragma unroll
  for (int m = 0; m < 16; ++m) acc[m] = 0.f;

  for (int c = 0; c < 4; ++c) {
    __syncthreads();
    for (int i = tid; i < 4096; i += 128) sW[i] = W2[c * 4096 + i];
    __syncthreads();
    int k0 = c * 32;
#pragma unroll 8
    for (int k = 0; k < 32; ++k) {
      float w = sW[k * 128 + tid];
#pragma unroll
      for (int m = 0; m < 16; ++m) acc[m] = fmaf(sIn[m * 128 + k0 + k], w, acc[m]);
    }
  }

  int head = tid >> 5, lane = tid & 31;
#pragma unroll
  for (int m = 0; m < 16; ++m) {
    int n = base + m;
    float a = acc[m];
    float vs = warpsum(a * sAs[tid]);
    float vd = warpsum(a * sAd[tid]);
    if (n < N) {
      g_h2[(size_t)n * 128 + tid] = a;
      if (lane == 0) {
        float* ps = (float*)&g_asrc2[n];
        float* pd = (float*)&g_adst2[n];
        ps[head] = vs;
        pd[head] = vd;
      }
    }
  }
}

// ---------------- GAT aggregation: warp per destination node ----------------
// mode 0: layer1 -> g_out1 = relu(agg + bias1)   (device symbol, NOT a param!)
// mode 1: layer2 -> dout[n] = relu(mean_h agg + b2) . wlin + blin
__global__ void gat_aggregate_kernel(float* __restrict__ dout,
                                     const float* __restrict__ bias,
                                     const float* __restrict__ wlin,
                                     const float* __restrict__ blin,
                                     int N, int mode) {
  int gw = (blockIdx.x * blockDim.x + threadIdx.x) >> 5;
  int lane = threadIdx.x & 31;
  if (gw >= N) return;

  const float*  h     = (mode == 0) ? g_h1 : g_h2;
  const float4* asrc4 = (mode == 0) ? g_asrc1 : g_asrc2;
  const float4* adst4 = (mode == 0) ? g_adst1 : g_adst2;

  int rs = g_rowptr[gw], re = g_rowptr[gw + 1];
  float4 ad = adst4[gw];

  // pass 1: softmax denominators per head (no max-shift; |e| is small here)
  float d0 = 0.f, d1 = 0.f, d2 = 0.f, d3 = 0.f;
  for (int i = rs + lane; i < re; i += 32) {
    float4 as = asrc4[g_colsrc[i]];
    float e0 = as.x + ad.x; e0 = e0 > 0.f ? e0 : 0.2f * e0;
    float e1 = as.y + ad.y; e1 = e1 > 0.f ? e1 : 0.2f * e1;
    float e2 = as.z + ad.z; e2 = e2 > 0.f ? e2 : 0.2f * e2;
    float e3 = as.w + ad.w; e3 = e3 > 0.f ? e3 : 0.2f * e3;
    d0 += __expf(e0); d1 += __expf(e1); d2 += __expf(e2); d3 += __expf(e3);
  }
  d0 = warpsum(d0); d1 = warpsum(d1); d2 = warpsum(d2); d3 = warpsum(d3);

  int head = lane >> 3;  // lane owns channels [4*lane, 4*lane+4) -> head = lane/8
  float rd  = 1.0f / (head == 0 ? d0 : head == 1 ? d1 : head == 2 ? d2 : d3);
  float adh = (head == 0 ? ad.x : head == 1 ? ad.y : head == 2 ? ad.z : ad.w);

  // pass 2: weighted aggregation (one LDG.128 per lane per edge)
  float ax = 0.f, ay = 0.f, az = 0.f, aw = 0.f;
  for (int i = rs; i < re; ++i) {
    int s = g_colsrc[i];   // broadcast across warp
    float4 as = asrc4[s];  // broadcast
    float ah = (head == 0 ? as.x : head == 1 ? as.y : head == 2 ? as.z : as.w);
    float e = ah + adh; e = e > 0.f ? e : 0.2f * e;
    float alpha = __expf(e) * rd;
    float4 hv = *(const float4*)(h + (size_t)s * 128 + lane * 4);
    ax = fmaf(hv.x, alpha, ax);
    ay = fmaf(hv.y, alpha, ay);
    az = fmaf(hv.z, alpha, az);
    aw = fmaf(hv.w, alpha, aw);
  }

  if (mode == 0) {
    float4 b = ((const float4*)bias)[lane];  // harness buffer: 256B aligned
    float4 o;
    o.x = fmaxf(ax + b.x, 0.f);
    o.y = fmaxf(ay + b.y, 0.f);
    o.z = fmaxf(az + b.z, 0.f);
    o.w = fmaxf(aw + b.w, 0.f);
    // write through the DEVICE symbol, not a host-passed pointer
    *(float4*)(g_out1 + (size_t)gw * 128 + lane * 4) = o;
  } else {
    // sum over the 4 heads: lanes l, l^8, l^16, l^24 hold identical channels
    ax += __shfl_xor_sync(0xffffffffu, ax, 8);
    ax += __shfl_xor_sync(0xffffffffu, ax, 16);
    ay += __shfl_xor_sync(0xffffffffu, ay, 8);
    ay += __shfl_xor_sync(0xffffffffu, ay, 16);
    az += __shfl_xor_sync(0xffffffffu, az, 8);
    az += __shfl_xor_sync(0xffffffffu, az, 16);
    aw += __shfl_xor_sync(0xffffffffu, aw, 8);
    aw += __shfl_xor_sync(0xffffffffu, aw, 16);
    int c0 = (lane & 7) * 4;
    float v0 = fmaxf(ax * 0.25f + bias[c0 + 0], 0.f);
    float v1 = fmaxf(ay * 0.25f + bias[c0 + 1], 0.f);
    float v2 = fmaxf(az * 0.25f + bias[c0 + 2], 0.f);
    float v3 = fmaxf(aw * 0.25f + bias[c0 + 3], 0.f);
    float p = v0 * wlin[c0] + v1 * wlin[c0 + 1] + v2 * wlin[c0 + 2] + v3 * wlin[c0 + 3];
    p += __shfl_xor_sync(0xffffffffu, p, 1);
    p += __shfl_xor_sync(0xffffffffu, p, 2);
    p += __shfl_xor_sync(0xffffffffu, p, 4);
    if (lane == 0) dout[gw] = p + blin[0];
  }
}

// ---------------- launch -----------------------------------------------------
extern "C" void kernel_launch(void* const* d_in, const int* in_sizes, int n_in,
                              void* d_out, int out_size) {
  const float* x    = (const float*)d_in[0];
  const int*   ei   = (const int*)d_in[1];
  const float* W1   = (const float*)d_in[2];
  const float* as1  = (const float*)d_in[3];
  const float* ad1  = (const float*)d_in[4];
  const float* b1   = (const float*)d_in[5];
  const float* W2   = (const float*)d_in[6];
  const float* as2  = (const float*)d_in[7];
  const float* ad2  = (const float*)d_in[8];
  const float* b2   = (const float*)d_in[9];
  const float* wlin = (const float*)d_in[10];
  const float* blin = (const float*)d_in[11];

  int N = in_sizes[0] / 8;
  int E = in_sizes[1] / 2;
  const int* srcv = ei;
  const int* dstv = ei + E;

  // CSR build (graph identical for both layers)
  init_count_kernel<<<(N + 255) / 256, 256>>>(N);
  hist_kernel<<<(E + 255) / 256, 256>>>(dstv, E);
  scan_kernel<<<1, 1024>>>(N);
  scatter_kernel<<<(E + N + 255) / 256, 256>>>(srcv, dstv, E, N);

  // layer 1 (aggregate writes g_out1 internally)
  gemm1_kernel<<<(N + 7) / 8, 128>>>(x, W1, as1, ad1, N);
  gat_aggregate_kernel<<<(N + 7) / 8, 256>>>((float*)d_out, b1, nullptr, nullptr, N, 0);

  // layer 2 + fused head-mean/bias/relu/linear epilogue
  gemm2_kernel<<<(N + 15) / 16, 128>>>(W2, as2, ad2, N);
  gat_aggregate_kernel<<<(N + 7) / 8, 256>>>((float*)d_out, b2, wlin, blin, N, 1);
}

// round 4
// speedup vs baseline: 1.1683x; 1.1683x over previous
#include <cuda_runtime.h>

// Problem-shape upper bounds (N=100000, E=1600000 for this dataset).
#define NMAX 100000
#define EMAX 1600000

// ---------------- scratch (static device globals; 16B-aligned for LDG.128) --
__device__ __align__(16) float g_h1[(size_t)NMAX * 128];    // layer1 features
__device__ __align__(16) float g_out1[(size_t)NMAX * 128];  // relu(gat1 + b1)
__device__ __align__(16) float g_h2[(size_t)NMAX * 128];    // layer2 features
__device__ float4 g_asrc1[NMAX];
__device__ float4 g_adst1[NMAX];
__device__ float4 g_asrc2[NMAX];
__device__ float4 g_adst2[NMAX];
__device__ int    g_count[NMAX];
__device__ int    g_rowptr[NMAX + 1];
__device__ int    g_cursor[NMAX];
__device__ int    g_colsrc[EMAX + NMAX];  // CSR column (src) indices, dst-sorted

__device__ __forceinline__ float warpsum(float v) {
  v += __shfl_xor_sync(0xffffffffu, v, 16);
  v += __shfl_xor_sync(0xffffffffu, v, 8);
  v += __shfl_xor_sync(0xffffffffu, v, 4);
  v += __shfl_xor_sync(0xffffffffu, v, 2);
  v += __shfl_xor_sync(0xffffffffu, v, 1);
  return v;
}

__device__ __forceinline__ float lrelu(float e) { return e > 0.f ? e : 0.2f * e; }

__device__ __forceinline__ float headsel(float4 v, int head) {
  return head == 0 ? v.x : head == 1 ? v.y : head == 2 ? v.z : v.w;
}

// ---------------- CSR build --------------------------------------------------
__global__ void init_count_kernel(int N) {
  int i = blockIdx.x * blockDim.x + threadIdx.x;
  if (i < N) g_count[i] = 1;  // 1 accounts for the self-loop
}

__global__ void hist_kernel(const int* __restrict__ dstv, int E) {
  int i = blockIdx.x * blockDim.x + threadIdx.x;
  if (i < E) atomicAdd(&g_count[dstv[i]], 1);
}

// Single-block exclusive scan of g_count -> g_rowptr (+ cursor copy).
__global__ void scan_kernel(int N) {
  __shared__ int s[1024];
  int t = threadIdx.x;
  int CH = (N + 1023) >> 10;
  int b0 = t * CH;
  int b1 = b0 + CH; if (b1 > N) b1 = N;
  int sum = 0;
  for (int i = b0; i < b1; ++i) sum += g_count[i];
  s[t] = sum;
  __syncthreads();
  for (int off = 1; off < 1024; off <<= 1) {
    int v = (t >= off) ? s[t - off] : 0;
    __syncthreads();
    s[t] += v;
    __syncthreads();
  }
  int run = s[t] - sum;  // exclusive prefix
  for (int i = b0; i < b1; ++i) {
    g_rowptr[i] = run;
    g_cursor[i] = run;
    run += g_count[i];
  }
  if (t == 1023) g_rowptr[N] = s[1023];
}

__global__ void scatter_kernel(const int* __restrict__ srcv,
                               const int* __restrict__ dstv, int E, int N) {
  int i = blockIdx.x * blockDim.x + threadIdx.x;
  if (i < E) {
    int p = atomicAdd(&g_cursor[dstv[i]], 1);
    g_colsrc[p] = srcv[i];
  } else if (i < E + N) {
    int n = i - E;  // self loop
    int p = atomicAdd(&g_cursor[n], 1);
    g_colsrc[p] = n;
  }
}

// ---------------- layer-1 GEMM: h1 = x[N,8] @ W1[8,128]  (+ per-head a) -----
__global__ void gemm1_kernel(const float* __restrict__ x,
                             const float* __restrict__ W1,
                             const float* __restrict__ att_s,
                             const float* __restrict__ att_d, int N) {
  __shared__ float sW[8 * 128];
  __shared__ float sAs[128], sAd[128];
  int tid = threadIdx.x;  // 128 threads; tid = output column = head*32+ch
  for (int i = tid; i < 1024; i += 128) sW[i] = W1[i];
  sAs[tid] = att_s[tid];
  sAd[tid] = att_d[tid];
  __syncthreads();
  int head = tid >> 5, lane = tid & 31;
  int base = blockIdx.x * 8;
  for (int m = 0; m < 8; ++m) {
    int n = base + m;
    if (n >= N) break;  // uniform across block
    float acc = 0.f;
#pragma unroll
    for (int k = 0; k < 8; ++k) acc = fmaf(__ldg(&x[n * 8 + k]), sW[k * 128 + tid], acc);
    g_h1[(size_t)n * 128 + tid] = acc;
    float vs = warpsum(acc * sAs[tid]);
    float vd = warpsum(acc * sAd[tid]);
    if (lane == 0) {
      float* ps = (float*)&g_asrc1[n];
      float* pd = (float*)&g_adst1[n];
      ps[head] = vs;
      pd[head] = vd;
    }
  }
}

// ---------------- layer-2 GEMM: h2 = out1[N,128] @ W2[128,128] (+ a) --------
// 256 threads; lane owns 4 cols (float4), warp owns 8 nodes; 64 nodes/block.
// Inner loop: 1 LDS.128 + 8 broadcast LDS per 32 FFMA -> near FFMA floor.
__global__ void gemm2_kernel(const float* __restrict__ W2,
                             const float* __restrict__ att_s,
                             const float* __restrict__ att_d, int N) {
  __shared__ __align__(16) float sW[16 * 128];   // one 16-row K chunk (8KB)
  __shared__ __align__(16) float sIn[64 * 128];  // 64 input rows (32KB)
  __shared__ float4 sAs4[32], sAd4[32];
  int tid = threadIdx.x;  // 256
  int warp = tid >> 5, lane = tid & 31;
  if (tid < 32) {
    sAs4[tid] = ((const float4*)att_s)[tid];
    sAd4[tid] = ((const float4*)att_d)[tid];
  }
  int base = blockIdx.x * 64;
  float4 zero4 = make_float4(0.f, 0.f, 0.f, 0.f);
  for (int idx = tid; idx < 2048; idx += 256) {
    int row = idx >> 5, c4 = idx & 31;
    int r = base + row;
    ((float4*)sIn)[idx] =
        (r < N) ? *(const float4*)(g_out1 + (size_t)r * 128 + c4 * 4) : zero4;
  }
  float4 acc[8];
#pragma unroll
  for (int m = 0; m < 8; ++m) acc[m] = zero4;
  const float* myIn = sIn + warp * 8 * 128;

  for (int c = 0; c < 8; ++c) {
    __syncthreads();
    for (int idx = tid; idx < 512; idx += 256)
      ((float4*)sW)[idx] = ((const float4*)W2)[c * 512 + idx];
    __syncthreads();
    int k0 = c * 16;
#pragma unroll
    for (int k = 0; k < 16; ++k) {
      float4 w = ((const float4*)sW)[k * 32 + lane];
#pragma unroll
      for (int m = 0; m < 8; ++m) {
        float v = myIn[m * 128 + k0 + k];  // broadcast
        acc[m].x = fmaf(v, w.x, acc[m].x);
        acc[m].y = fmaf(v, w.y, acc[m].y);
        acc[m].z = fmaf(v, w.z, acc[m].z);
        acc[m].w = fmaf(v, w.w, acc[m].w);
      }
    }
  }

  // epilogue: store h2 + per-head attention dots (8-lane segmented reduce)
  float4 as = sAs4[lane], ad = sAd4[lane];
  int head = lane >> 3;
#pragma unroll
  for (int m = 0; m < 8; ++m) {
    int n = base + warp * 8 + m;
    float4 a = acc[m];
    float ts = a.x * as.x + a.y * as.y + a.z * as.z + a.w * as.w;
    float td = a.x * ad.x + a.y * ad.y + a.z * ad.z + a.w * ad.w;
    ts += __shfl_xor_sync(0xffffffffu, ts, 1);
    ts += __shfl_xor_sync(0xffffffffu, ts, 2);
    ts += __shfl_xor_sync(0xffffffffu, ts, 4);
    td += __shfl_xor_sync(0xffffffffu, td, 1);
    td += __shfl_xor_sync(0xffffffffu, td, 2);
    td += __shfl_xor_sync(0xffffffffu, td, 4);
    if (n < N) {
      *(float4*)(g_h2 + (size_t)n * 128 + lane * 4) = a;
      if ((lane & 7) == 0) {
        ((float*)&g_asrc2[n])[head] = ts;
        ((float*)&g_adst2[n])[head] = td;
      }
    }
  }
}

// ---------------- GAT aggregation: warp per dst node, SINGLE pass -----------
// softmax = sum(exp(e)*h) / sum(exp(e))  (no max-shift; |e| is small here)
// mode 0: g_out1 = relu(agg + bias1)   (device symbol, NOT a param!)
// mode 1: dout[n] = relu(mean_h agg + b2) . wlin + blin
__global__ void gat_aggregate_kernel(float* __restrict__ dout,
                                     const float* __restrict__ bias,
                                     const float* __restrict__ wlin,
                                     const float* __restrict__ blin,
                                     int N, int mode) {
  int gw = (blockIdx.x * blockDim.x + threadIdx.x) >> 5;
  int lane = threadIdx.x & 31;
  if (gw >= N) return;

  const float*  h     = (mode == 0) ? g_h1 : g_h2;
  const float4* asrc4 = (mode == 0) ? g_asrc1 : g_asrc2;
  const float4* adst4 = (mode == 0) ? g_adst1 : g_adst2;

  int rs = g_rowptr[gw], re = g_rowptr[gw + 1];
  int head = lane >> 3;  // lane owns channels [4*lane, 4*lane+4)
  float adh = headsel(adst4[gw], head);

  float ax = 0.f, ay = 0.f, az = 0.f, aw = 0.f, den = 0.f;
  int i = rs;
  for (; i + 4 <= re; i += 4) {  // 4 independent gathers in flight
    int s0 = g_colsrc[i], s1 = g_colsrc[i + 1];
    int s2 = g_colsrc[i + 2], s3 = g_colsrc[i + 3];
    float4 A0 = asrc4[s0], A1 = asrc4[s1], A2 = asrc4[s2], A3 = asrc4[s3];
    float al0 = __expf(lrelu(headsel(A0, head) + adh));
    float al1 = __expf(lrelu(headsel(A1, head) + adh));
    float al2 = __expf(lrelu(headsel(A2, head) + adh));
    float al3 = __expf(lrelu(headsel(A3, head) + adh));
    float4 h0 = *((const float4*)(h + (size_t)s0 * 128) + lane);
    float4 h1 = *((const float4*)(h + (size_t)s1 * 128) + lane);
    float4 h2 = *((const float4*)(h + (size_t)s2 * 128) + lane);
    float4 h3 = *((const float4*)(h + (size_t)s3 * 128) + lane);
    ax = fmaf(h0.x, al0, ax); ay = fmaf(h0.y, al0, ay);
    az = fmaf(h0.z, al0, az); aw = fmaf(h0.w, al0, aw);
    ax = fmaf(h1.x, al1, ax); ay = fmaf(h1.y, al1, ay);
    az = fmaf(h1.z, al1, az); aw = fmaf(h1.w, al1, aw);
    ax = fmaf(h2.x, al2, ax); ay = fmaf(h2.y, al2, ay);
    az = fmaf(h2.z, al2, az); aw = fmaf(h2.w, al2, aw);
    ax = fmaf(h3.x, al3, ax); ay = fmaf(h3.y, al3, ay);
    az = fmaf(h3.z, al3, az); aw = fmaf(h3.w, al3, aw);
    den += (al0 + al1) + (al2 + al3);
  }
  for (; i < re; ++i) {
    int s = g_colsrc[i];
    float al = __expf(lrelu(headsel(asrc4[s], head) + adh));
    float4 hv = *((const float4*)(h + (size_t)s * 128) + lane);
    ax = fmaf(hv.x, al, ax); ay = fmaf(hv.y, al, ay);
    az = fmaf(hv.z, al, az); aw = fmaf(hv.w, al, aw);
    den += al;
  }
  float rd = 1.0f / den;  // den identical across each head's 8 lanes
  ax *= rd; ay *= rd; az *= rd; aw *= rd;

  if (mode == 0) {
    float4 b = ((const float4*)bias)[lane];
    float4 o;
    o.x = fmaxf(ax + b.x, 0.f);
    o.y = fmaxf(ay + b.y, 0.f);
    o.z = fmaxf(az + b.z, 0.f);
    o.w = fmaxf(aw + b.w, 0.f);
    *(float4*)(g_out1 + (size_t)gw * 128 + lane * 4) = o;  // device symbol
  } else {
    // sum over the 4 heads: lanes l, l^8, l^16, l^24 hold identical channels
    ax += __shfl_xor_sync(0xffffffffu, ax, 8);
    ax += __shfl_xor_sync(0xffffffffu, ax, 16);
    ay += __shfl_xor_sync(0xffffffffu, ay, 8);
    ay += __shfl_xor_sync(0xffffffffu, ay, 16);
    az += __shfl_xor_sync(0xffffffffu, az, 8);
    az += __shfl_xor_sync(0xffffffffu, az, 16);
    aw += __shfl_xor_sync(0xffffffffu, aw, 8);
    aw += __shfl_xor_sync(0xffffffffu, aw, 16);
    int c0 = (lane & 7) * 4;
    float v0 = fmaxf(ax * 0.25f + bias[c0 + 0], 0.f);
    float v1 = fmaxf(ay * 0.25f + bias[c0 + 1], 0.f);
    float v2 = fmaxf(az * 0.25f + bias[c0 + 2], 0.f);
    float v3 = fmaxf(aw * 0.25f + bias[c0 + 3], 0.f);
    float p = v0 * wlin[c0] + v1 * wlin[c0 + 1] + v2 * wlin[c0 + 2] + v3 * wlin[c0 + 3];
    p += __shfl_xor_sync(0xffffffffu, p, 1);
    p += __shfl_xor_sync(0xffffffffu, p, 2);
    p += __shfl_xor_sync(0xffffffffu, p, 4);
    if (lane == 0) dout[gw] = p + blin[0];
  }
}

// ---------------- launch -----------------------------------------------------
extern "C" void kernel_launch(void* const* d_in, const int* in_sizes, int n_in,
                              void* d_out, int out_size) {
  const float* x    = (const float*)d_in[0];
  const int*   ei   = (const int*)d_in[1];
  const float* W1   = (const float*)d_in[2];
  const float* as1  = (const float*)d_in[3];
  const float* ad1  = (const float*)d_in[4];
  const float* b1   = (const float*)d_in[5];
  const float* W2   = (const float*)d_in[6];
  const float* as2  = (const float*)d_in[7];
  const float* ad2  = (const float*)d_in[8];
  const float* b2   = (const float*)d_in[9];
  const float* wlin = (const float*)d_in[10];
  const float* blin = (const float*)d_in[11];

  int N = in_sizes[0] / 8;
  int E = in_sizes[1] / 2;
  const int* srcv = ei;
  const int* dstv = ei + E;

  // CSR build (graph identical for both layers)
  init_count_kernel<<<(N + 255) / 256, 256>>>(N);
  hist_kernel<<<(E + 255) / 256, 256>>>(dstv, E);
  scan_kernel<<<1, 1024>>>(N);
  scatter_kernel<<<(E + N + 255) / 256, 256>>>(srcv, dstv, E, N);

  // layer 1 (aggregate writes g_out1 internally)
  gemm1_kernel<<<(N + 7) / 8, 128>>>(x, W1, as1, ad1, N);
  gat_aggregate_kernel<<<(N + 7) / 8, 256>>>((float*)d_out, b1, nullptr, nullptr, N, 0);

  // layer 2 + fused head-mean/bias/relu/linear epilogue
  gemm2_kernel<<<(N + 63) / 64, 256>>>(W2, as2, ad2, N);
  gat_aggregate_kernel<<<(N + 7) / 8, 256>>>((float*)d_out, b2, wlin, blin, N, 1);
}

// round 6
// speedup vs baseline: 1.1958x; 1.0236x over previous
#include <cuda_runtime.h>
#include <cuda_fp16.h>

// Problem-shape upper bounds (N=100000, E=1600000 for this dataset).
#define NMAX 100000
#define EMAX 1600000

// ---------------- scratch (static device globals) ---------------------------
__device__ __align__(16) __half g_h1h[(size_t)NMAX * 128];  // layer1 features (fp16)
__device__ __align__(16) __half g_h2h[(size_t)NMAX * 128];  // layer2 features (fp16)
__device__ __align__(16) float  g_out1[(size_t)NMAX * 128]; // relu(gat1 + b1) (fp32)
__device__ float4 g_asrc1[NMAX];
__device__ float4 g_adst1[NMAX];
__device__ float4 g_asrc2[NMAX];
__device__ float4 g_adst2[NMAX];
__device__ int    g_count[NMAX];
__device__ int    g_rowptr[NMAX + 1];
__device__ int    g_cursor[NMAX];
__device__ int    g_colsrc[EMAX + NMAX];  // CSR column (src) indices, dst-sorted

__device__ __forceinline__ float warpsum(float v) {
  v += __shfl_xor_sync(0xffffffffu, v, 16);
  v += __shfl_xor_sync(0xffffffffu, v, 8);
  v += __shfl_xor_sync(0xffffffffu, v, 4);
  v += __shfl_xor_sync(0xffffffffu, v, 2);
  v += __shfl_xor_sync(0xffffffffu, v, 1);
  return v;
}

__device__ __forceinline__ float lrelu(float e) { return e > 0.f ? e : 0.2f * e; }

__device__ __forceinline__ float headsel(float4 v, int head) {
  return head == 0 ? v.x : head == 1 ? v.y : head == 2 ? v.z : v.w;
}

// ---------------- CSR build --------------------------------------------------
__global__ void init_count_kernel(int N) {
  int i = blockIdx.x * blockDim.x + threadIdx.x;
  if (i < N) g_count[i] = 1;  // 1 accounts for the self-loop
}

__global__ void hist_kernel(const int* __restrict__ dstv, int E) {
  int i = blockIdx.x * blockDim.x + threadIdx.x;
  if (i < E) atomicAdd(&g_count[dstv[i]], 1);
}

// Single-block exclusive scan of g_count -> g_rowptr (+ cursor copy).
__global__ void scan_kernel(int N) {
  __shared__ int s[1024];
  int t = threadIdx.x;
  int CH = (N + 1023) >> 10;
  int b0 = t * CH;
  int b1 = b0 + CH; if (b1 > N) b1 = N;
  int sum = 0;
  for (int i = b0; i < b1; ++i) sum += g_count[i];
  s[t] = sum;
  __syncthreads();
  for (int off = 1; off < 1024; off <<= 1) {
    int v = (t >= off) ? s[t - off] : 0;
    __syncthreads();
    s[t] += v;
    __syncthreads();
  }
  int run = s[t] - sum;  // exclusive prefix
  for (int i = b0; i < b1; ++i) {
    g_rowptr[i] = run;
    g_cursor[i] = run;
    run += g_count[i];
  }
  if (t == 1023) g_rowptr[N] = s[1023];
}

__global__ void scatter_kernel(const int* __restrict__ srcv,
                               const int* __restrict__ dstv, int E, int N) {
  int i = blockIdx.x * blockDim.x + threadIdx.x;
  if (i < E) {
    int p = atomicAdd(&g_cursor[dstv[i]], 1);
    g_colsrc[p] = srcv[i];
  } else if (i < E + N) {
    int n = i - E;  // self loop
    int p = atomicAdd(&g_cursor[n], 1);
    g_colsrc[p] = n;
  }
}

// ---------------- layer-1 GEMM: h1 = x[N,8] @ W1[8,128]  (+ per-head a) -----
__global__ void gemm1_kernel(const float* __restrict__ x,
                             const float* __restrict__ W1,
                             const float* __restrict__ att_s,
                             const float* __restrict__ att_d, int N) {
  __shared__ float sW[8 * 128];
  __shared__ float sAs[128], sAd[128];
  int tid = threadIdx.x;  // 128 threads; tid = output column = head*32+ch
  for (int i = tid; i < 1024; i += 128) sW[i] = W1[i];
  sAs[tid] = att_s[tid];
  sAd[tid] = att_d[tid];
  __syncthreads();
  int head = tid >> 5, lane = tid & 31;
  int base = blockIdx.x * 8;
  for (int m = 0; m < 8; ++m) {
    int n = base + m;
    if (n >= N) break;  // uniform across block
    float acc = 0.f;
#pragma unroll
    for (int k = 0; k < 8; ++k) acc = fmaf(__ldg(&x[n * 8 + k]), sW[k * 128 + tid], acc);
    g_h1h[(size_t)n * 128 + tid] = __float2half(acc);
    float vs = warpsum(acc * sAs[tid]);
    float vd = warpsum(acc * sAd[tid]);
    if (lane == 0) {
      float* ps = (float*)&g_asrc1[n];
      float* pd = (float*)&g_adst1[n];
      ps[head] = vs;
      pd[head] = vd;
    }
  }
}

// ---------------- layer-2 GEMM: h2 = out1[N,128] @ W2[128,128] (+ a) --------
// 256 threads; lane owns 4 cols (float4), warp owns 8 nodes; 64 nodes/block.
__global__ void gemm2_kernel(const float* __restrict__ W2,
                             const float* __restrict__ att_s,
                             const float* __restrict__ att_d, int N) {
  __shared__ __align__(16) float sW[16 * 128];   // one 16-row K chunk (8KB)
  __shared__ __align__(16) float sIn[64 * 128];  // 64 input rows (32KB)
  __shared__ float4 sAs4[32], sAd4[32];
  int tid = threadIdx.x;  // 256
  int warp = tid >> 5, lane = tid & 31;
  if (tid < 32) {
    sAs4[tid] = ((const float4*)att_s)[tid];
    sAd4[tid] = ((const float4*)att_d)[tid];
  }
  int base = blockIdx.x * 64;
  float4 zero4 = make_float4(0.f, 0.f, 0.f, 0.f);
  for (int idx = tid; idx < 2048; idx += 256) {
    int row = idx >> 5, c4 = idx & 31;
    int r = base + row;
    ((float4*)sIn)[idx] =
        (r < N) ? *(const float4*)(g_out1 + (size_t)r * 128 + c4 * 4) : zero4;
  }
  float4 acc[8];
#pragma unroll
  for (int m = 0; m < 8; ++m) acc[m] = zero4;
  const float* myIn = sIn + warp * 8 * 128;

  for (int c = 0; c < 8; ++c) {
    __syncthreads();
    for (int idx = tid; idx < 512; idx += 256)
      ((float4*)sW)[idx] = ((const float4*)W2)[c * 512 + idx];
    __syncthreads();
    int k0 = c * 16;
#pragma unroll
    for (int k = 0; k < 16; ++k) {
      float4 w = ((const float4*)sW)[k * 32 + lane];
#pragma unroll
      for (int m = 0; m < 8; ++m) {
        float v = myIn[m * 128 + k0 + k];  // broadcast
        acc[m].x = fmaf(v, w.x, acc[m].x);
        acc[m].y = fmaf(v, w.y, acc[m].y);
        acc[m].z = fmaf(v, w.z, acc[m].z);
        acc[m].w = fmaf(v, w.w, acc[m].w);
      }
    }
  }

  // epilogue: store h2 (fp16) + per-head attention dots (8-lane segmented reduce)
  float4 as = sAs4[lane], ad = sAd4[lane];
  int head = lane >> 3;
#pragma unroll
  for (int m = 0; m < 8; ++m) {
    int n = base + warp * 8 + m;
    float4 a = acc[m];
    float ts = a.x * as.x + a.y * as.y + a.z * as.z + a.w * as.w;
    float td = a.x * ad.x + a.y * ad.y + a.z * ad.z + a.w * ad.w;
    ts += __shfl_xor_sync(0xffffffffu, ts, 1);
    ts += __shfl_xor_sync(0xffffffffu, ts, 2);
    ts += __shfl_xor_sync(0xffffffffu, ts, 4);
    td += __shfl_xor_sync(0xffffffffu, td, 1);
    td += __shfl_xor_sync(0xffffffffu, td, 2);
    td += __shfl_xor_sync(0xffffffffu, td, 4);
    if (n < N) {
      __half2 lo = __floats2half2_rn(a.x, a.y);
      __half2 hi = __floats2half2_rn(a.z, a.w);
      uint2 packed;
      packed.x = *(unsigned*)&lo;
      packed.y = *(unsigned*)&hi;
      *(uint2*)(g_h2h + (size_t)n * 128 + lane * 4) = packed;
      if ((lane & 7) == 0) {
        ((float*)&g_asrc2[n])[head] = ts;
        ((float*)&g_adst2[n])[head] = td;
      }
    }
  }
}

// ---------------- GAT aggregation: warp per dst node, single pass -----------
// features gathered in fp16 (256 B/edge instead of 512 B); math in fp32.
// mode 0: g_out1 = relu(agg + bias1)   (device symbol)
// mode 1: dout[n] = relu(mean_h agg + b2) . wlin + blin
__device__ __forceinline__ void acc_h4(const __half* __restrict__ hh, int s,
                                       int lane, float al,
                                       float& ax, float& ay, float& az, float& aw) {
  uint2 u = *(const uint2*)(hh + (size_t)s * 128 + lane * 4);
  __half2 p0 = *(__half2*)&u.x;
  __half2 p1 = *(__half2*)&u.y;
  float2 f0 = __half22float2(p0);
  float2 f1 = __half22float2(p1);
  ax = fmaf(f0.x, al, ax);
  ay = fmaf(f0.y, al, ay);
  az = fmaf(f1.x, al, az);
  aw = fmaf(f1.y, al, aw);
}

__global__ void gat_aggregate_kernel(float* __restrict__ dout,
                                     const float* __restrict__ bias,
                                     const float* __restrict__ wlin,
                                     const float* __restrict__ blin,
                                     int N, int mode) {
  int gw = (blockIdx.x * blockDim.x + threadIdx.x) >> 5;
  int lane = threadIdx.x & 31;
  if (gw >= N) return;

  const __half* hh    = (mode == 0) ? g_h1h : g_h2h;
  const float4* asrc4 = (mode == 0) ? g_asrc1 : g_asrc2;
  const float4* adst4 = (mode == 0) ? g_adst1 : g_adst2;

  int rs = g_rowptr[gw], re = g_rowptr[gw + 1];
  int head = lane >> 3;  // lane owns channels [4*lane, 4*lane+4)
  float adh = headsel(adst4[gw], head);

  float ax = 0.f, ay = 0.f, az = 0.f, aw = 0.f, den = 0.f;
  int i = rs;
  for (; i + 4 <= re; i += 4) {  // 4 independent gathers in flight
    int s0 = g_colsrc[i], s1 = g_colsrc[i + 1];
    int s2 = g_colsrc[i + 2], s3 = g_colsrc[i + 3];
    float4 A0 = asrc4[s0], A1 = asrc4[s1], A2 = asrc4[s2], A3 = asrc4[s3];
    float al0 = __expf(lrelu(headsel(A0, head) + adh));
    float al1 = __expf(lrelu(headsel(A1, head) + adh));
    float al2 = __expf(lrelu(headsel(A2, head) + adh));
    float al3 = __expf(lrelu(headsel(A3, head) + adh));
    acc_h4(hh, s0, lane, al0, ax, ay, az, aw);
    acc_h4(hh, s1, lane, al1, ax, ay, az, aw);
    acc_h4(hh, s2, lane, al2, ax, ay, az, aw);
    acc_h4(hh, s3, lane, al3, ax, ay, az, aw);
    den += (al0 + al1) + (al2 + al3);
  }
  for (; i < re; ++i) {
    int s = g_colsrc[i];
    float al = __expf(lrelu(headsel(asrc4[s], head) + adh));
    acc_h4(hh, s, lane, al, ax, ay, az, aw);
    den += al;
  }
  float rd = 1.0f / den;  // den identical across each head's 8 lanes
  ax *= rd; ay *= rd; az *= rd; aw *= rd;

  if (mode == 0) {
    float4 b = ((const float4*)bias)[lane];
    float4 o;
    o.x = fmaxf(ax + b.x, 0.f);
    o.y = fmaxf(ay + b.y, 0.f);
    o.z = fmaxf(az + b.z, 0.f);
    o.w = fmaxf(aw + b.w, 0.f);
    *(float4*)(g_out1 + (size_t)gw * 128 + lane * 4) = o;  // device symbol
  } else {
    // sum over the 4 heads: lanes l, l^8, l^16, l^24 hold identical channels
    ax += __shfl_xor_sync(0xffffffffu, ax, 8);
    ax += __shfl_xor_sync(0xffffffffu, ax, 16);
    ay += __shfl_xor_sync(0xffffffffu, ay, 8);
    ay += __shfl_xor_sync(0xffffffffu, ay, 16);
    az += __shfl_xor_sync(0xffffffffu, az, 8);
    az += __shfl_xor_sync(0xffffffffu, az, 16);
    aw += __shfl_xor_sync(0xffffffffu, aw, 8);
    aw += __shfl_xor_sync(0xffffffffu, aw, 16);
    int c0 = (lane & 7) * 4;
    float v0 = fmaxf(ax * 0.25f + bias[c0 + 0], 0.f);
    float v1 = fmaxf(ay * 0.25f + bias[c0 + 1], 0.f);
    float v2 = fmaxf(az * 0.25f + bias[c0 + 2], 0.f);
    float v3 = fmaxf(aw * 0.25f + bias[c0 + 3], 0.f);
    float p = v0 * wlin[c0] + v1 * wlin[c0 + 1] + v2 * wlin[c0 + 2] + v3 * wlin[c0 + 3];
    p += __shfl_xor_sync(0xffffffffu, p, 1);
    p += __shfl_xor_sync(0xffffffffu, p, 2);
    p += __shfl_xor_sync(0xffffffffu, p, 4);
    if (lane == 0) dout[gw] = p + blin[0];
  }
}

// ---------------- launch -----------------------------------------------------
extern "C" void kernel_launch(void* const* d_in, const int* in_sizes, int n_in,
                              void* d_out, int out_size) {
  const float* x    = (const float*)d_in[0];
  const int*   ei   = (const int*)d_in[1];
  const float* W1   = (const float*)d_in[2];
  const float* as1  = (const float*)d_in[3];
  const float* ad1  = (const float*)d_in[4];
  const float* b1   = (const float*)d_in[5];
  const float* W2   = (const float*)d_in[6];
  const float* as2  = (const float*)d_in[7];
  const float* ad2  = (const float*)d_in[8];
  const float* b2   = (const float*)d_in[9];
  const float* wlin = (const float*)d_in[10];
  const float* blin = (const float*)d_in[11];

  int N = in_sizes[0] / 8;
  int E = in_sizes[1] / 2;
  const int* srcv = ei;
  const int* dstv = ei + E;

  // CSR build (graph identical for both layers)
  init_count_kernel<<<(N + 255) / 256, 256>>>(N);
  hist_kernel<<<(E + 255) / 256, 256>>>(dstv, E);
  scan_kernel<<<1, 1024>>>(N);
  scatter_kernel<<<(E + N + 255) / 256, 256>>>(srcv, dstv, E, N);

  // layer 1 (aggregate writes g_out1 internally)
  gemm1_kernel<<<(N + 7) / 8, 128>>>(x, W1, as1, ad1, N);
  gat_aggregate_kernel<<<(N + 7) / 8, 256>>>((float*)d_out, b1, nullptr, nullptr, N, 0);

  // layer 2 + fused head-mean/bias/relu/linear epilogue
  gemm2_kernel<<<(N + 63) / 64, 256>>>(W2, as2, ad2, N);
  gat_aggregate_kernel<<<(N + 7) / 8, 256>>>((float*)d_out, b2, wlin, blin, N, 1);
}

// round 7
// speedup vs baseline: 1.2821x; 1.0722x over previous
#include <cuda_runtime.h>
#include <cuda_fp16.h>

// Problem-shape upper bounds (N=100000, E=1600000 for this dataset).
#define NMAX 100000
#define EMAX 1600000

// ---------------- scratch (static device globals) ---------------------------
__device__ __align__(16) __half g_h1h[(size_t)NMAX * 128];  // layer1 features (fp16)
__device__ __align__(16) __half g_h2h[(size_t)NMAX * 128];  // layer2 features (fp16)
__device__ __align__(16) float  g_out1[(size_t)NMAX * 128]; // relu(gat1 + b1) (fp32)
__device__ float4 g_asrc1[NMAX];
__device__ float4 g_adst1[NMAX];
__device__ float4 g_asrc2[NMAX];
__device__ float4 g_adst2[NMAX];
__device__ int    g_count[NMAX];
__device__ int    g_rowptr[NMAX + 1];
__device__ int    g_cursor[NMAX];
__device__ int    g_colsrc[EMAX + NMAX];  // CSR column (src) indices, dst-sorted

__device__ __forceinline__ float warpsum(float v) {
  v += __shfl_xor_sync(0xffffffffu, v, 16);
  v += __shfl_xor_sync(0xffffffffu, v, 8);
  v += __shfl_xor_sync(0xffffffffu, v, 4);
  v += __shfl_xor_sync(0xffffffffu, v, 2);
  v += __shfl_xor_sync(0xffffffffu, v, 1);
  return v;
}

__device__ __forceinline__ float lrelu(float e) { return e > 0.f ? e : 0.2f * e; }

// ---------------- CSR build --------------------------------------------------
__global__ void init_count_kernel(int N) {
  int i = blockIdx.x * blockDim.x + threadIdx.x;
  if (i < N) g_count[i] = 1;  // 1 accounts for the self-loop
}

__global__ void hist_kernel(const int* __restrict__ dstv, int E) {
  int i = blockIdx.x * blockDim.x + threadIdx.x;
  if (i < E) atomicAdd(&g_count[dstv[i]], 1);
}

// Single-block exclusive scan of g_count -> g_rowptr (+ cursor copy).
__global__ void scan_kernel(int N) {
  __shared__ int s[1024];
  int t = threadIdx.x;
  int CH = (N + 1023) >> 10;
  int b0 = t * CH;
  int b1 = b0 + CH; if (b1 > N) b1 = N;
  int sum = 0;
  for (int i = b0; i < b1; ++i) sum += g_count[i];
  s[t] = sum;
  __syncthreads();
  for (int off = 1; off < 1024; off <<= 1) {
    int v = (t >= off) ? s[t - off] : 0;
    __syncthreads();
    s[t] += v;
    __syncthreads();
  }
  int run = s[t] - sum;  // exclusive prefix
  for (int i = b0; i < b1; ++i) {
    g_rowptr[i] = run;
    g_cursor[i] = run;
    run += g_count[i];
  }
  if (t == 1023) g_rowptr[N] = s[1023];
}

__global__ void scatter_kernel(const int* __restrict__ srcv,
                               const int* __restrict__ dstv, int E, int N) {
  int i = blockIdx.x * blockDim.x + threadIdx.x;
  if (i < E) {
    int p = atomicAdd(&g_cursor[dstv[i]], 1);
    g_colsrc[p] = srcv[i];
  } else if (i < E + N) {
    int n = i - E;  // self loop
    int p = atomicAdd(&g_cursor[n], 1);
    g_colsrc[p] = n;
  }
}

// ---------------- layer-1 GEMM: h1 = x[N,8] @ W1[8,128]  (+ per-head a) -----
__global__ void gemm1_kernel(const float* __restrict__ x,
                             const float* __restrict__ W1,
                             const float* __restrict__ att_s,
                             const float* __restrict__ att_d, int N) {
  __shared__ float sW[8 * 128];
  __shared__ float sAs[128], sAd[128];
  int tid = threadIdx.x;  // 128 threads; tid = output column = head*32+ch
  for (int i = tid; i < 1024; i += 128) sW[i] = W1[i];
  sAs[tid] = att_s[tid];
  sAd[tid] = att_d[tid];
  __syncthreads();
  int head = tid >> 5, lane = tid & 31;
  int base = blockIdx.x * 8;
  for (int m = 0; m < 8; ++m) {
    int n = base + m;
    if (n >= N) break;  // uniform across block
    float acc = 0.f;
#pragma unroll
    for (int k = 0; k < 8; ++k) acc = fmaf(__ldg(&x[n * 8 + k]), sW[k * 128 + tid], acc);
    g_h1h[(size_t)n * 128 + tid] = __float2half(acc);
    float vs = warpsum(acc * sAs[tid]);
    float vd = warpsum(acc * sAd[tid]);
    if (lane == 0) {
      float* ps = (float*)&g_asrc1[n];
      float* pd = (float*)&g_adst1[n];
      ps[head] = vs;
      pd[head] = vd;
    }
  }
}

// ---------------- layer-2 GEMM: h2 = out1[N,128] @ W2[128,128] (+ a) --------
// 256 threads; lane owns 4 cols (float4), warp owns 8 nodes; 64 nodes/block.
__global__ void gemm2_kernel(const float* __restrict__ W2,
                             const float* __restrict__ att_s,
                             const float* __restrict__ att_d, int N) {
  __shared__ __align__(16) float sW[16 * 128];   // one 16-row K chunk (8KB)
  __shared__ __align__(16) float sIn[64 * 128];  // 64 input rows (32KB)
  __shared__ float4 sAs4[32], sAd4[32];
  int tid = threadIdx.x;  // 256
  int warp = tid >> 5, lane = tid & 31;
  if (tid < 32) {
    sAs4[tid] = ((const float4*)att_s)[tid];
    sAd4[tid] = ((const float4*)att_d)[tid];
  }
  int base = blockIdx.x * 64;
  float4 zero4 = make_float4(0.f, 0.f, 0.f, 0.f);
  for (int idx = tid; idx < 2048; idx += 256) {
    int row = idx >> 5, c4 = idx & 31;
    int r = base + row;
    ((float4*)sIn)[idx] =
        (r < N) ? *(const float4*)(g_out1 + (size_t)r * 128 + c4 * 4) : zero4;
  }
  float4 acc[8];
#pragma unroll
  for (int m = 0; m < 8; ++m) acc[m] = zero4;
  const float* myIn = sIn + warp * 8 * 128;

  for (int c = 0; c < 8; ++c) {
    __syncthreads();
    for (int idx = tid; idx < 512; idx += 256)
      ((float4*)sW)[idx] = ((const float4*)W2)[c * 512 + idx];
    __syncthreads();
    int k0 = c * 16;
#pragma unroll
    for (int k = 0; k < 16; ++k) {
      float4 w = ((const float4*)sW)[k * 32 + lane];
#pragma unroll
      for (int m = 0; m < 8; ++m) {
        float v = myIn[m * 128 + k0 + k];  // broadcast
        acc[m].x = fmaf(v, w.x, acc[m].x);
        acc[m].y = fmaf(v, w.y, acc[m].y);
        acc[m].z = fmaf(v, w.z, acc[m].z);
        acc[m].w = fmaf(v, w.w, acc[m].w);
      }
    }
  }

  // epilogue: store h2 (fp16) + per-head attention dots (8-lane segmented reduce)
  float4 as = sAs4[lane], ad = sAd4[lane];
  int head = lane >> 3;
#pragma unroll
  for (int m = 0; m < 8; ++m) {
    int n = base + warp * 8 + m;
    float4 a = acc[m];
    float ts = a.x * as.x + a.y * as.y + a.z * as.z + a.w * as.w;
    float td = a.x * ad.x + a.y * ad.y + a.z * ad.z + a.w * ad.w;
    ts += __shfl_xor_sync(0xffffffffu, ts, 1);
    ts += __shfl_xor_sync(0xffffffffu, ts, 2);
    ts += __shfl_xor_sync(0xffffffffu, ts, 4);
    td += __shfl_xor_sync(0xffffffffu, td, 1);
    td += __shfl_xor_sync(0xffffffffu, td, 2);
    td += __shfl_xor_sync(0xffffffffu, td, 4);
    if (n < N) {
      __half2 lo = __floats2half2_rn(a.x, a.y);
      __half2 hi = __floats2half2_rn(a.z, a.w);
      uint2 packed;
      packed.x = *(unsigned*)&lo;
      packed.y = *(unsigned*)&hi;
      *(uint2*)(g_h2h + (size_t)n * 128 + lane * 4) = packed;
      if ((lane & 7) == 0) {
        ((float*)&g_asrc2[n])[head] = ts;
        ((float*)&g_adst2[n])[head] = td;
      }
    }
  }
}

// ---------------- GAT aggregation: warp per dst node, single pass -----------
// Edge ids prefetched cooperatively (1 coalesced LDG per 32 edges, shfl
// broadcast) -> only ONE L2 trip per edge. 8x unroll => 16 gathers in flight.
__device__ __forceinline__ void acc_h4(const __half* __restrict__ hh, int s,
                                       int lane, float al,
                                       float& ax, float& ay, float& az, float& aw) {
  uint2 u = *(const uint2*)(hh + (size_t)s * 128 + lane * 4);
  __half2 p0 = *(__half2*)&u.x;
  __half2 p1 = *(__half2*)&u.y;
  float2 f0 = __half22float2(p0);
  float2 f1 = __half22float2(p1);
  ax = fmaf(f0.x, al, ax);
  ay = fmaf(f0.y, al, ay);
  az = fmaf(f1.x, al, az);
  aw = fmaf(f1.y, al, aw);
}

__global__ void gat_aggregate_kernel(float* __restrict__ dout,
                                     const float* __restrict__ bias,
                                     const float* __restrict__ wlin,
                                     const float* __restrict__ blin,
                                     int N, int mode) {
  int gw = (blockIdx.x * blockDim.x + threadIdx.x) >> 5;
  int lane = threadIdx.x & 31;
  if (gw >= N) return;

  const __half* hh    = (mode == 0) ? g_h1h : g_h2h;
  const float*  asrcf = (const float*)((mode == 0) ? g_asrc1 : g_asrc2);
  const float*  adstf = (const float*)((mode == 0) ? g_adst1 : g_adst2);

  int rs = g_rowptr[gw], re = g_rowptr[gw + 1];
  int head = lane >> 3;  // lane owns channels [4*lane, 4*lane+4)
  float adh = __ldg(&adstf[gw * 4 + head]);

  float ax = 0.f, ay = 0.f, az = 0.f, aw = 0.f, den = 0.f;

  for (int c = rs; c < re; c += 32) {
    int cnt = re - c; if (cnt > 32) cnt = 32;
    int idx = c + lane;
    int sv = g_colsrc[idx < re ? idx : re - 1];  // coalesced prefetch
    int j = 0;
    for (; j + 8 <= cnt; j += 8) {
      int s[8];
#pragma unroll
      for (int u = 0; u < 8; ++u) s[u] = __shfl_sync(0xffffffffu, sv, j + u);
      float av[8];
#pragma unroll
      for (int u = 0; u < 8; ++u) av[u] = __ldg(&asrcf[s[u] * 4 + head]);
      float al[8];
#pragma unroll
      for (int u = 0; u < 8; ++u) al[u] = __expf(lrelu(av[u] + adh));
#pragma unroll
      for (int u = 0; u < 8; ++u) {
        acc_h4(hh, s[u], lane, al[u], ax, ay, az, aw);
        den += al[u];
      }
    }
    for (; j < cnt; ++j) {
      int s0 = __shfl_sync(0xffffffffu, sv, j);
      float al = __expf(lrelu(__ldg(&asrcf[s0 * 4 + head]) + adh));
      acc_h4(hh, s0, lane, al, ax, ay, az, aw);
      den += al;
    }
  }
  float rd = 1.0f / den;  // den identical across each head's 8 lanes
  ax *= rd; ay *= rd; az *= rd; aw *= rd;

  if (mode == 0) {
    float4 b = ((const float4*)bias)[lane];
    float4 o;
    o.x = fmaxf(ax + b.x, 0.f);
    o.y = fmaxf(ay + b.y, 0.f);
    o.z = fmaxf(az + b.z, 0.f);
    o.w = fmaxf(aw + b.w, 0.f);
    *(float4*)(g_out1 + (size_t)gw * 128 + lane * 4) = o;  // device symbol
  } else {
    // sum over the 4 heads: lanes l, l^8, l^16, l^24 hold identical channels
    ax += __shfl_xor_sync(0xffffffffu, ax, 8);
    ax += __shfl_xor_sync(0xffffffffu, ax, 16);
    ay += __shfl_xor_sync(0xffffffffu, ay, 8);
    ay += __shfl_xor_sync(0xffffffffu, ay, 16);
    az += __shfl_xor_sync(0xffffffffu, az, 8);
    az += __shfl_xor_sync(0xffffffffu, az, 16);
    aw += __shfl_xor_sync(0xffffffffu, aw, 8);
    aw += __shfl_xor_sync(0xffffffffu, aw, 16);
    int c0 = (lane & 7) * 4;
    float v0 = fmaxf(ax * 0.25f + bias[c0 + 0], 0.f);
    float v1 = fmaxf(ay * 0.25f + bias[c0 + 1], 0.f);
    float v2 = fmaxf(az * 0.25f + bias[c0 + 2], 0.f);
    float v3 = fmaxf(aw * 0.25f + bias[c0 + 3], 0.f);
    float p = v0 * wlin[c0] + v1 * wlin[c0 + 1] + v2 * wlin[c0 + 2] + v3 * wlin[c0 + 3];
    p += __shfl_xor_sync(0xffffffffu, p, 1);
    p += __shfl_xor_sync(0xffffffffu, p, 2);
    p += __shfl_xor_sync(0xffffffffu, p, 4);
    if (lane == 0) dout[gw] = p + blin[0];
  }
}

// ---------------- launch -----------------------------------------------------
extern "C" void kernel_launch(void* const* d_in, const int* in_sizes, int n_in,
                              void* d_out, int out_size) {
  const float* x    = (const float*)d_in[0];
  const int*   ei   = (const int*)d_in[1];
  const float* W1   = (const float*)d_in[2];
  const float* as1  = (const float*)d_in[3];
  const float* ad1  = (const float*)d_in[4];
  const float* b1   = (const float*)d_in[5];
  const float* W2   = (const float*)d_in[6];
  const float* as2  = (const float*)d_in[7];
  const float* ad2  = (const float*)d_in[8];
  const float* b2   = (const float*)d_in[9];
  const float* wlin = (const float*)d_in[10];
  const float* blin = (const float*)d_in[11];

  int N = in_sizes[0] / 8;
  int E = in_sizes[1] / 2;
  const int* srcv = ei;
  const int* dstv = ei + E;

  // CSR build (graph identical for both layers)
  init_count_kernel<<<(N + 255) / 256, 256>>>(N);
  hist_kernel<<<(E + 255) / 256, 256>>>(dstv, E);
  scan_kernel<<<1, 1024>>>(N);
  scatter_kernel<<<(E + N + 255) / 256, 256>>>(srcv, dstv, E, N);

  // layer 1 (aggregate writes g_out1 internally)
  gemm1_kernel<<<(N + 7) / 8, 128>>>(x, W1, as1, ad1, N);
  gat_aggregate_kernel<<<(N + 7) / 8, 256>>>((float*)d_out, b1, nullptr, nullptr, N, 0);

  // layer 2 + fused head-mean/bias/relu/linear epilogue
  gemm2_kernel<<<(N + 63) / 64, 256>>>(W2, as2, ad2, N);
  gat_aggregate_kernel<<<(N + 7) / 8, 256>>>((float*)d_out, b2, wlin, blin, N, 1);
}

// round 8
// speedup vs baseline: 1.4307x; 1.1159x over previous
#include <cuda_runtime.h>
#include <cuda_fp16.h>
#include <cstdint>

// Problem-shape upper bounds (N=100000, E=1600000 for this dataset).
#define NMAX 100000
#define EMAX 1600000

// ---------------- scratch (static device globals) ---------------------------
__device__ __align__(16) __half g_h1h[(size_t)NMAX * 128];   // layer1 features (fp16)
__device__ __align__(16) __half g_h2h[(size_t)NMAX * 128];   // layer2 features (fp16)
__device__ __align__(16) __half g_out1h[(size_t)NMAX * 128]; // relu(gat1+b1) (fp16)
__device__ float4 g_asrc1[NMAX];
__device__ float4 g_adst1[NMAX];
__device__ float4 g_asrc2[NMAX];
__device__ float4 g_adst2[NMAX];
__device__ int    g_count[NMAX];
__device__ int    g_rowptr[NMAX + 1];
__device__ int    g_cursor[NMAX];
__device__ int    g_colsrc[EMAX + NMAX];  // CSR column (src) indices, dst-sorted

__device__ __forceinline__ float warpsum(float v) {
  v += __shfl_xor_sync(0xffffffffu, v, 16);
  v += __shfl_xor_sync(0xffffffffu, v, 8);
  v += __shfl_xor_sync(0xffffffffu, v, 4);
  v += __shfl_xor_sync(0xffffffffu, v, 2);
  v += __shfl_xor_sync(0xffffffffu, v, 1);
  return v;
}

__device__ __forceinline__ float lrelu(float e) { return e > 0.f ? e : 0.2f * e; }

__device__ __forceinline__ uint32_t smem_u32(const void* p) {
  return (uint32_t)__cvta_generic_to_shared(p);
}

__device__ __forceinline__ void ldsm_x4(uint32_t& r0, uint32_t& r1, uint32_t& r2,
                                        uint32_t& r3, uint32_t addr) {
  asm volatile("ldmatrix.sync.aligned.m8n8.x4.shared.b16 {%0,%1,%2,%3}, [%4];"
               : "=r"(r0), "=r"(r1), "=r"(r2), "=r"(r3) : "r"(addr));
}

__device__ __forceinline__ void ldsm_x4_t(uint32_t& r0, uint32_t& r1, uint32_t& r2,
                                          uint32_t& r3, uint32_t addr) {
  asm volatile("ldmatrix.sync.aligned.m8n8.x4.trans.shared.b16 {%0,%1,%2,%3}, [%4];"
               : "=r"(r0), "=r"(r1), "=r"(r2), "=r"(r3) : "r"(addr));
}

__device__ __forceinline__ void mma16816(float& d0, float& d1, float& d2, float& d3,
                                         uint32_t a0, uint32_t a1, uint32_t a2,
                                         uint32_t a3, uint32_t b0, uint32_t b1) {
  asm volatile(
      "mma.sync.aligned.m16n8k16.row.col.f32.f16.f16.f32 "
      "{%0,%1,%2,%3}, {%4,%5,%6,%7}, {%8,%9}, {%0,%1,%2,%3};"
      : "+f"(d0), "+f"(d1), "+f"(d2), "+f"(d3)
      : "r"(a0), "r"(a1), "r"(a2), "r"(a3), "r"(b0), "r"(b1));
}

// ---------------- CSR build --------------------------------------------------
__global__ void init_count_kernel(int N) {
  int i = blockIdx.x * blockDim.x + threadIdx.x;
  if (i < N) g_count[i] = 1;  // 1 accounts for the self-loop
}

__global__ void hist_kernel(const int* __restrict__ dstv, int E) {
  int i = blockIdx.x * blockDim.x + threadIdx.x;
  if (i < E) atomicAdd(&g_count[dstv[i]], 1);
}

__global__ void scan_kernel(int N) {
  __shared__ int s[1024];
  int t = threadIdx.x;
  int CH = (N + 1023) >> 10;
  int b0 = t * CH;
  int b1 = b0 + CH; if (b1 > N) b1 = N;
  int sum = 0;
  for (int i = b0; i < b1; ++i) sum += g_count[i];
  s[t] = sum;
  __syncthreads();
  for (int off = 1; off < 1024; off <<= 1) {
    int v = (t >= off) ? s[t - off] : 0;
    __syncthreads();
    s[t] += v;
    __syncthreads();
  }
  int run = s[t] - sum;  // exclusive prefix
  for (int i = b0; i < b1; ++i) {
    g_rowptr[i] = run;
    g_cursor[i] = run;
    run += g_count[i];
  }
  if (t == 1023) g_rowptr[N] = s[1023];
}

__global__ void scatter_kernel(const int* __restrict__ srcv,
                               const int* __restrict__ dstv, int E, int N) {
  int i = blockIdx.x * blockDim.x + threadIdx.x;
  if (i < E) {
    int p = atomicAdd(&g_cursor[dstv[i]], 1);
    g_colsrc[p] = srcv[i];
  } else if (i < E + N) {
    int n = i - E;  // self loop
    int p = atomicAdd(&g_cursor[n], 1);
    g_colsrc[p] = n;
  }
}

// ---------------- layer-1 GEMM: h1 = x[N,8] @ W1[8,128]  (+ per-head a) -----
__global__ void gemm1_kernel(const float* __restrict__ x,
                             const float* __restrict__ W1,
                             const float* __restrict__ att_s,
                             const float* __restrict__ att_d, int N) {
  __shared__ float sW[8 * 128];
  __shared__ float sAs[128], sAd[128];
  int tid = threadIdx.x;  // 128 threads; tid = output column = head*32+ch
  for (int i = tid; i < 1024; i += 128) sW[i] = W1[i];
  sAs[tid] = att_s[tid];
  sAd[tid] = att_d[tid];
  __syncthreads();
  int head = tid >> 5, lane = tid & 31;
  int base = blockIdx.x * 8;
  for (int m = 0; m < 8; ++m) {
    int n = base + m;
    if (n >= N) break;  // uniform across block
    float acc = 0.f;
#pragma unroll
    for (int k = 0; k < 8; ++k) acc = fmaf(__ldg(&x[n * 8 + k]), sW[k * 128 + tid], acc);
    g_h1h[(size_t)n * 128 + tid] = __float2half(acc);
    float vs = warpsum(acc * sAs[tid]);
    float vd = warpsum(acc * sAd[tid]);
    if (lane == 0) {
      float* ps = (float*)&g_asrc1[n];
      float* pd = (float*)&g_adst1[n];
      ps[head] = vs;
      pd[head] = vd;
    }
  }
}

// ---------------- layer-2 GEMM via HMMA tensor cores ------------------------
// h2[32nodes,128] = out1h[32,128] @ W2h[128,128]; fp16 in, fp32 accum.
// 8 warps in 2(M)x4(N); warp tile m16 x n32; K = 8 steps of k16.
// XOR swizzle on 16B chunks: chunk' = chunk ^ (row & 7)  -> conflict-free LDSM.
__global__ void gemm2_kernel(const float* __restrict__ W2,
                             const float* __restrict__ att_s,
                             const float* __restrict__ att_d, int N) {
  __shared__ __align__(16) __half sA[32 * 128];   // 8KB; reused as C (fp16)
  __shared__ __align__(16) __half sB[128 * 128];  // 32KB (W2 fp16, swizzled)
  __shared__ float4 sAs4[32], sAd4[32];
  int tid = threadIdx.x;  // 256
  int warp = tid >> 5, lane = tid & 31;
  int base = blockIdx.x * 32;

  if (tid < 32) {
    sAs4[tid] = ((const float4*)att_s)[tid];
    sAd4[tid] = ((const float4*)att_d)[tid];
  }

  // load W2 -> sB (fp16, swizzled): 2048 chunks of 16B (8 halves)
  for (int idx = tid; idx < 2048; idx += 256) {
    int k = idx >> 4, ch = idx & 15;
    const float4* src = (const float4*)(W2 + k * 128 + ch * 8);
    float4 w0 = src[0], w1 = src[1];
    __half2 p0 = __floats2half2_rn(w0.x, w0.y);
    __half2 p1 = __floats2half2_rn(w0.z, w0.w);
    __half2 p2 = __floats2half2_rn(w1.x, w1.y);
    __half2 p3 = __floats2half2_rn(w1.z, w1.w);
    uint4 v = make_uint4(*(unsigned*)&p0, *(unsigned*)&p1,
                         *(unsigned*)&p2, *(unsigned*)&p3);
    *(uint4*)(sB + k * 128 + ((ch ^ (k & 7)) << 3)) = v;
  }
  // load A rows (out1h fp16) -> sA swizzled: 512 chunks
  for (int idx = tid; idx < 512; idx += 256) {
    int r = idx >> 4, ch = idx & 15;
    int node = base + r;
    uint4 v = make_uint4(0u, 0u, 0u, 0u);
    if (node < N) v = *(const uint4*)(g_out1h + (size_t)node * 128 + ch * 8);
    *(uint4*)(sA + r * 128 + ((ch ^ (r & 7)) << 3)) = v;
  }
  __syncthreads();

  int wr = warp & 1;   // M: rows wr*16..+16
  int wc = warp >> 1;  // N: cols wc*32..+32
  int grp = lane >> 3; // ldmatrix address group

  // fixed per-lane pieces
  int a_row = wr * 16 + (lane & 7) + ((grp & 1) << 3);         // 0..31
  int b_krow_off = (lane & 7) + ((grp & 1) << 3);              // within k16
  uint32_t sA_base = smem_u32(sA);
  uint32_t sB_base = smem_u32(sB);

  float d[4][4];
#pragma unroll
  for (int t = 0; t < 4; ++t)
#pragma unroll
    for (int j = 0; j < 4; ++j) d[t][j] = 0.f;

#pragma unroll
  for (int kk = 0; kk < 8; ++kk) {
    // A fragment (m16 x k16)
    int a_ch = kk * 2 + (grp >> 1);
    uint32_t aaddr = sA_base + (uint32_t)(a_row * 256 + ((a_ch ^ (a_row & 7)) << 4));
    uint32_t a0, a1, a2, a3;
    ldsm_x4(a0, a1, a2, a3, aaddr);

    // B fragments for 4 n-tiles (two x4.trans loads, n16 each)
    int k_row = kk * 16 + b_krow_off;
    int cb0 = wc * 4 + (grp >> 1);
    uint32_t baddr0 = sB_base + (uint32_t)(k_row * 256 + ((cb0 ^ (k_row & 7)) << 4));
    uint32_t baddr1 = sB_base + (uint32_t)(k_row * 256 + (((cb0 + 2) ^ (k_row & 7)) << 4));
    uint32_t b0, b1, b2, b3, b4, b5, b6, b7;
    ldsm_x4_t(b0, b1, b2, b3, baddr0);
    ldsm_x4_t(b4, b5, b6, b7, baddr1);

    mma16816(d[0][0], d[0][1], d[0][2], d[0][3], a0, a1, a2, a3, b0, b1);
    mma16816(d[1][0], d[1][1], d[1][2], d[1][3], a0, a1, a2, a3, b2, b3);
    mma16816(d[2][0], d[2][1], d[2][2], d[2][3], a0, a1, a2, a3, b4, b5);
    mma16816(d[3][0], d[3][1], d[3][2], d[3][3], a0, a1, a2, a3, b6, b7);
  }
  __syncthreads();  // all LDSM from sA done before overwrite

  // write C fragments as fp16 into sA (plain row-major: row*128 halves)
  {
    int crow = wr * 16 + (lane >> 2);
    int ccol0 = wc * 32 + (lane & 3) * 2;
#pragma unroll
    for (int t = 0; t < 4; ++t) {
      int c = ccol0 + t * 8;
      __half2 lo = __floats2half2_rn(d[t][0], d[t][1]);
      __half2 hi = __floats2half2_rn(d[t][2], d[t][3]);
      *(__half2*)(sA + crow * 128 + c) = lo;
      *(__half2*)(sA + (crow + 8) * 128 + c) = hi;
    }
  }
  __syncthreads();

  // epilogue: warp handles 4 nodes; lane owns 4 cols
  float4 as = sAs4[lane], ad = sAd4[lane];
  int head = lane >> 3;
#pragma unroll
  for (int m = 0; m < 4; ++m) {
    int r = warp * 4 + m;
    int n = base + r;
    uint2 u = *(uint2*)(sA + r * 128 + lane * 4);
    __half2 p0 = *(__half2*)&u.x;
    __half2 p1 = *(__half2*)&u.y;
    float2 f0 = __half22float2(p0);
    float2 f1 = __half22float2(p1);
    float ts = f0.x * as.x + f0.y * as.y + f1.x * as.z + f1.y * as.w;
    float td = f0.x * ad.x + f0.y * ad.y + f1.x * ad.z + f1.y * ad.w;
    ts += __shfl_xor_sync(0xffffffffu, ts, 1);
    ts += __shfl_xor_sync(0xffffffffu, ts, 2);
    ts += __shfl_xor_sync(0xffffffffu, ts, 4);
    td += __shfl_xor_sync(0xffffffffu, td, 1);
    td += __shfl_xor_sync(0xffffffffu, td, 2);
    td += __shfl_xor_sync(0xffffffffu, td, 4);
    if (n < N) {
      *(uint2*)(g_h2h + (size_t)n * 128 + lane * 4) = u;
      if ((lane & 7) == 0) {
        ((float*)&g_asrc2[n])[head] = ts;
        ((float*)&g_adst2[n])[head] = td;
      }
    }
  }
}

// ---------------- GAT aggregation: warp per dst node, single pass -----------
__device__ __forceinline__ void acc_h4(const __half* __restrict__ hh, int s,
                                       int lane, float al,
                                       float& ax, float& ay, float& az, float& aw) {
  uint2 u = *(const uint2*)(hh + (size_t)s * 128 + lane * 4);
  __half2 p0 = *(__half2*)&u.x;
  __half2 p1 = *(__half2*)&u.y;
  float2 f0 = __half22float2(p0);
  float2 f1 = __half22float2(p1);
  ax = fmaf(f0.x, al, ax);
  ay = fmaf(f0.y, al, ay);
  az = fmaf(f1.x, al, az);
  aw = fmaf(f1.y, al, aw);
}

__global__ void gat_aggregate_kernel(float* __restrict__ dout,
                                     const float* __restrict__ bias,
                                     const float* __restrict__ wlin,
                                     const float* __restrict__ blin,
                                     int N, int mode) {
  int gw = (blockIdx.x * blockDim.x + threadIdx.x) >> 5;
  int lane = threadIdx.x & 31;
  if (gw >= N) return;

  const __half* hh    = (mode == 0) ? g_h1h : g_h2h;
  const float*  asrcf = (const float*)((mode == 0) ? g_asrc1 : g_asrc2);
  const float*  adstf = (const float*)((mode == 0) ? g_adst1 : g_adst2);

  int rs = g_rowptr[gw], re = g_rowptr[gw + 1];
  int head = lane >> 3;  // lane owns channels [4*lane, 4*lane+4)
  float adh = __ldg(&adstf[gw * 4 + head]);

  float ax = 0.f, ay = 0.f, az = 0.f, aw = 0.f, den = 0.f;

  for (int c = rs; c < re; c += 32) {
    int cnt = re - c; if (cnt > 32) cnt = 32;
    int idx = c + lane;
    int sv = g_colsrc[idx < re ? idx : re - 1];  // coalesced prefetch
    int j = 0;
    for (; j + 8 <= cnt; j += 8) {
      int s[8];
#pragma unroll
      for (int u = 0; u < 8; ++u) s[u] = __shfl_sync(0xffffffffu, sv, j + u);
      float av[8];
#pragma unroll
      for (int u = 0; u < 8; ++u) av[u] = __ldg(&asrcf[s[u] * 4 + head]);
      float al[8];
#pragma unroll
      for (int u = 0; u < 8; ++u) al[u] = __expf(lrelu(av[u] + adh));
#pragma unroll
      for (int u = 0; u < 8; ++u) {
        acc_h4(hh, s[u], lane, al[u], ax, ay, az, aw);
        den += al[u];
      }
    }
    for (; j < cnt; ++j) {
      int s0 = __shfl_sync(0xffffffffu, sv, j);
      float al = __expf(lrelu(__ldg(&asrcf[s0 * 4 + head]) + adh));
      acc_h4(hh, s0, lane, al, ax, ay, az, aw);
      den += al;
    }
  }
  float rd = 1.0f / den;  // den identical across each head's 8 lanes
  ax *= rd; ay *= rd; az *= rd; aw *= rd;

  if (mode == 0) {
    float4 b = ((const float4*)bias)[lane];
    __half2 lo = __floats2half2_rn(fmaxf(ax + b.x, 0.f), fmaxf(ay + b.y, 0.f));
    __half2 hi = __floats2half2_rn(fmaxf(az + b.z, 0.f), fmaxf(aw + b.w, 0.f));
    uint2 packed;
    packed.x = *(unsigned*)&lo;
    packed.y = *(unsigned*)&hi;
    *(uint2*)(g_out1h + (size_t)gw * 128 + lane * 4) = packed;  // device symbol
  } else {
    // sum over the 4 heads: lanes l, l^8, l^16, l^24 hold identical channels
    ax += __shfl_xor_sync(0xffffffffu, ax, 8);
    ax += __shfl_xor_sync(0xffffffffu, ax, 16);
    ay += __shfl_xor_sync(0xffffffffu, ay, 8);
    ay += __shfl_xor_sync(0xffffffffu, ay, 16);
    az += __shfl_xor_sync(0xffffffffu, az, 8);
    az += __shfl_xor_sync(0xffffffffu, az, 16);
    aw += __shfl_xor_sync(0xffffffffu, aw, 8);
    aw += __shfl_xor_sync(0xffffffffu, aw, 16);
    int c0 = (lane & 7) * 4;
    float v0 = fmaxf(ax * 0.25f + bias[c0 + 0], 0.f);
    float v1 = fmaxf(ay * 0.25f + bias[c0 + 1], 0.f);
    float v2 = fmaxf(az * 0.25f + bias[c0 + 2], 0.f);
    float v3 = fmaxf(aw * 0.25f + bias[c0 + 3], 0.f);
    float p = v0 * wlin[c0] + v1 * wlin[c0 + 1] + v2 * wlin[c0 + 2] + v3 * wlin[c0 + 3];
    p += __shfl_xor_sync(0xffffffffu, p, 1);
    p += __shfl_xor_sync(0xffffffffu, p, 2);
    p += __shfl_xor_sync(0xffffffffu, p, 4);
    if (lane == 0) dout[gw] = p + blin[0];
  }
}

// ---------------- launch -----------------------------------------------------
extern "C" void kernel_launch(void* const* d_in, const int* in_sizes, int n_in,
                              void* d_out, int out_size) {
  const float* x    = (const float*)d_in[0];
  const int*   ei   = (const int*)d_in[1];
  const float* W1   = (const float*)d_in[2];
  const float* as1  = (const float*)d_in[3];
  const float* ad1  = (const float*)d_in[4];
  const float* b1   = (const float*)d_in[5];
  const float* W2   = (const float*)d_in[6];
  const float* as2  = (const float*)d_in[7];
  const float* ad2  = (const float*)d_in[8];
  const float* b2   = (const float*)d_in[9];
  const float* wlin = (const float*)d_in[10];
  const float* blin = (const float*)d_in[11];

  int N = in_sizes[0] / 8;
  int E = in_sizes[1] / 2;
  const int* srcv = ei;
  const int* dstv = ei + E;

  // CSR build (graph identical for both layers)
  init_count_kernel<<<(N + 255) / 256, 256>>>(N);
  hist_kernel<<<(E + 255) / 256, 256>>>(dstv, E);
  scan_kernel<<<1, 1024>>>(N);
  scatter_kernel<<<(E + N + 255) / 256, 256>>>(srcv, dstv, E, N);

  // layer 1 (aggregate writes g_out1h internally)
  gemm1_kernel<<<(N + 7) / 8, 128>>>(x, W1, as1, ad1, N);
  gat_aggregate_kernel<<<(N + 7) / 8, 256>>>((float*)d_out, b1, nullptr, nullptr, N, 0);

  // layer 2: tensor-core GEMM + fused epilogues
  gemm2_kernel<<<(N + 31) / 32, 256>>>(W2, as2, ad2, N);
  gat_aggregate_kernel<<<(N + 7) / 8, 256>>>((float*)d_out, b2, wlin, blin, N, 1);
}

// round 9
// speedup vs baseline: 2.2086x; 1.5437x over previous
#include <cuda_runtime.h>
#include <cuda_fp16.h>
#include <cstdint>

// Problem-shape upper bounds (N=100000, E=1600000 for this dataset).
#define NMAX 100000
#define EMAX 1600000
#define STILE 4096  // scan tile: 1024 threads x int4

// ---------------- scratch (static device globals) ---------------------------
__device__ __align__(16) __half g_h1h[(size_t)NMAX * 128];   // layer1 features (fp16)
__device__ __align__(16) __half g_h2h[(size_t)NMAX * 128];   // layer2 features (fp16)
__device__ __align__(16) __half g_out1h[(size_t)NMAX * 128]; // relu(gat1+b1) (fp16)
__device__ float4 g_asrc1[NMAX];
__device__ float4 g_adst1[NMAX];
__device__ float4 g_asrc2[NMAX];
__device__ float4 g_adst2[NMAX];
__device__ __align__(16) int g_count[NMAX + 4];
__device__ __align__(16) int g_rowptr[NMAX + 8];
__device__ __align__(16) int g_cursor[NMAX + 8];
__device__ int g_part[64];                 // per-tile sums for the scan
__device__ int g_colsrc[EMAX + NMAX];      // CSR column (src) indices, dst-sorted

__device__ __forceinline__ float warpsum(float v) {
  v += __shfl_xor_sync(0xffffffffu, v, 16);
  v += __shfl_xor_sync(0xffffffffu, v, 8);
  v += __shfl_xor_sync(0xffffffffu, v, 4);
  v += __shfl_xor_sync(0xffffffffu, v, 2);
  v += __shfl_xor_sync(0xffffffffu, v, 1);
  return v;
}

__device__ __forceinline__ float lrelu(float e) { return e > 0.f ? e : 0.2f * e; }

__device__ __forceinline__ uint32_t smem_u32(const void* p) {
  return (uint32_t)__cvta_generic_to_shared(p);
}

__device__ __forceinline__ void ldsm_x4(uint32_t& r0, uint32_t& r1, uint32_t& r2,
                                        uint32_t& r3, uint32_t addr) {
  asm volatile("ldmatrix.sync.aligned.m8n8.x4.shared.b16 {%0,%1,%2,%3}, [%4];"
               : "=r"(r0), "=r"(r1), "=r"(r2), "=r"(r3) : "r"(addr));
}

__device__ __forceinline__ void ldsm_x4_t(uint32_t& r0, uint32_t& r1, uint32_t& r2,
                                          uint32_t& r3, uint32_t addr) {
  asm volatile("ldmatrix.sync.aligned.m8n8.x4.trans.shared.b16 {%0,%1,%2,%3}, [%4];"
               : "=r"(r0), "=r"(r1), "=r"(r2), "=r"(r3) : "r"(addr));
}

__device__ __forceinline__ void mma16816(float& d0, float& d1, float& d2, float& d3,
                                         uint32_t a0, uint32_t a1, uint32_t a2,
                                         uint32_t a3, uint32_t b0, uint32_t b1) {
  asm volatile(
      "mma.sync.aligned.m16n8k16.row.col.f32.f16.f16.f32 "
      "{%0,%1,%2,%3}, {%4,%5,%6,%7}, {%8,%9}, {%0,%1,%2,%3};"
      : "+f"(d0), "+f"(d1), "+f"(d2), "+f"(d3)
      : "r"(a0), "r"(a1), "r"(a2), "r"(a3), "r"(b0), "r"(b1));
}

// ---------------- CSR build --------------------------------------------------
__global__ void init_count_kernel(int N) {
  int i = blockIdx.x * blockDim.x + threadIdx.x;
  if (i < N + 4) g_count[i] = (i < N) ? 1 : 0;  // 1 accounts for the self-loop
}

__global__ void hist_kernel(const int* __restrict__ dstv, int E) {
  int i = blockIdx.x * blockDim.x + threadIdx.x;
  if (i < E) atomicAdd(&g_count[dstv[i]], 1);
}

// -------- coalesced 3-phase exclusive scan of g_count -> g_rowptr/g_cursor --
// Phase A: per-tile sums (int4 coalesced loads, smem tree reduce)
__global__ void scanA_kernel(int N) {
  __shared__ int red[1024];
  int b = blockIdx.x, t = threadIdx.x;
  int base = b * STILE + t * 4;
  int s = 0;
  if (base < N) {  // g_count padded with zeros past N
    int4 v = *(const int4*)&g_count[base];
    s = v.x + v.y + v.z + v.w;
  }
  red[t] = s;
  __syncthreads();
  for (int off = 512; off > 0; off >>= 1) {
    if (t < off) red[t] += red[t + off];
    __syncthreads();
  }
  if (t == 0) g_part[b] = red[0];
}

// Phase B: exclusive scan of tile sums (tiny, single thread)
__global__ void scanB_kernel(int nb, int N) {
  if (threadIdx.x == 0) {
    int run = 0;
    for (int i = 0; i < nb; ++i) {
      int v = g_part[i];
      g_part[i] = run;
      run += v;
    }
    g_rowptr[N] = run;
  }
}

// Phase C: in-tile scan + coalesced int4 writes of rowptr/cursor
__global__ void scanC_kernel(int N) {
  __shared__ int s[1024];
  int b = blockIdx.x, t = threadIdx.x;
  int base = b * STILE + t * 4;
  int4 v = make_int4(0, 0, 0, 0);
  if (base < N) v = *(const int4*)&g_count[base];
  int mysum = v.x + v.y + v.z + v.w;
  s[t] = mysum;
  __syncthreads();
  for (int off = 1; off < 1024; off <<= 1) {
    int u = (t >= off) ? s[t - off] : 0;
    __syncthreads();
    s[t] += u;
    __syncthreads();
  }
  int run = g_part[b] + s[t] - mysum;  // exclusive prefix for this thread
  int4 p;
  p.x = run;
  p.y = p.x + v.x;
  p.z = p.y + v.y;
  p.w = p.z + v.z;
  if (base < N) {  // arrays padded; stray writes past N land in pad
    *(int4*)&g_rowptr[base] = p;
    *(int4*)&g_cursor[base] = p;
  }
}

__global__ void scatter_kernel(const int* __restrict__ srcv,
                               const int* __restrict__ dstv, int E, int N) {
  int i = blockIdx.x * blockDim.x + threadIdx.x;
  if (i < E) {
    int p = atomicAdd(&g_cursor[dstv[i]], 1);
    g_colsrc[p] = srcv[i];
  } else if (i < E + N) {
    int n = i - E;  // self loop
    int p = atomicAdd(&g_cursor[n], 1);
    g_colsrc[p] = n;
  }
}

// ---------------- layer-1 GEMM: h1 = x[N,8] @ W1[8,128]  (+ per-head a) -----
__global__ void gemm1_kernel(const float* __restrict__ x,
                             const float* __restrict__ W1,
                             const float* __restrict__ att_s,
                             const float* __restrict__ att_d, int N) {
  __shared__ float sW[8 * 128];
  __shared__ float sAs[128], sAd[128];
  int tid = threadIdx.x;  // 128 threads; tid = output column = head*32+ch
  for (int i = tid; i < 1024; i += 128) sW[i] = W1[i];
  sAs[tid] = att_s[tid];
  sAd[tid] = att_d[tid];
  __syncthreads();
  int head = tid >> 5, lane = tid & 31;
  int base = blockIdx.x * 8;
  for (int m = 0; m < 8; ++m) {
    int n = base + m;
    if (n >= N) break;  // uniform across block
    float acc = 0.f;
#pragma unroll
    for (int k = 0; k < 8; ++k) acc = fmaf(__ldg(&x[n * 8 + k]), sW[k * 128 + tid], acc);
    g_h1h[(size_t)n * 128 + tid] = __float2half(acc);
    float vs = warpsum(acc * sAs[tid]);
    float vd = warpsum(acc * sAd[tid]);
    if (lane == 0) {
      float* ps = (float*)&g_asrc1[n];
      float* pd = (float*)&g_adst1[n];
      ps[head] = vs;
      pd[head] = vd;
    }
  }
}

// ---------------- layer-2 GEMM via HMMA tensor cores ------------------------
__global__ void gemm2_kernel(const float* __restrict__ W2,
                             const float* __restrict__ att_s,
                             const float* __restrict__ att_d, int N) {
  __shared__ __align__(16) __half sA[32 * 128];   // 8KB; reused as C (fp16)
  __shared__ __align__(16) __half sB[128 * 128];  // 32KB (W2 fp16, swizzled)
  __shared__ float4 sAs4[32], sAd4[32];
  int tid = threadIdx.x;  // 256
  int warp = tid >> 5, lane = tid & 31;
  int base = blockIdx.x * 32;

  if (tid < 32) {
    sAs4[tid] = ((const float4*)att_s)[tid];
    sAd4[tid] = ((const float4*)att_d)[tid];
  }

  for (int idx = tid; idx < 2048; idx += 256) {
    int k = idx >> 4, ch = idx & 15;
    const float4* src = (const float4*)(W2 + k * 128 + ch * 8);
    float4 w0 = src[0], w1 = src[1];
    __half2 p0 = __floats2half2_rn(w0.x, w0.y);
    __half2 p1 = __floats2half2_rn(w0.z, w0.w);
    __half2 p2 = __floats2half2_rn(w1.x, w1.y);
    __half2 p3 = __floats2half2_rn(w1.z, w1.w);
    uint4 v = make_uint4(*(unsigned*)&p0, *(unsigned*)&p1,
                         *(unsigned*)&p2, *(unsigned*)&p3);
    *(uint4*)(sB + k * 128 + ((ch ^ (k & 7)) << 3)) = v;
  }
  for (int idx = tid; idx < 512; idx += 256) {
    int r = idx >> 4, ch = idx & 15;
    int node = base + r;
    uint4 v = make_uint4(0u, 0u, 0u, 0u);
    if (node < N) v = *(const uint4*)(g_out1h + (size_t)node * 128 + ch * 8);
    *(uint4*)(sA + r * 128 + ((ch ^ (r & 7)) << 3)) = v;
  }
  __syncthreads();

  int wr = warp & 1;   // M: rows wr*16..+16
  int wc = warp >> 1;  // N: cols wc*32..+32
  int grp = lane >> 3;

  int a_row = wr * 16 + (lane & 7) + ((grp & 1) << 3);
  int b_krow_off = (lane & 7) + ((grp & 1) << 3);
  uint32_t sA_base = smem_u32(sA);
  uint32_t sB_base = smem_u32(sB);

  float d[4][4];
#pragma unroll
  for (int t = 0; t < 4; ++t)
#pragma unroll
    for (int j = 0; j < 4; ++j) d[t][j] = 0.f;

#pragma unroll
  for (int kk = 0; kk < 8; ++kk) {
    int a_ch = kk * 2 + (grp >> 1);
    uint32_t aaddr = sA_base + (uint32_t)(a_row * 256 + ((a_ch ^ (a_row & 7)) << 4));
    uint32_t a0, a1, a2, a3;
    ldsm_x4(a0, a1, a2, a3, aaddr);

    int k_row = kk * 16 + b_krow_off;
    int cb0 = wc * 4 + (grp >> 1);
    uint32_t baddr0 = sB_base + (uint32_t)(k_row * 256 + ((cb0 ^ (k_row & 7)) << 4));
    uint32_t baddr1 = sB_base + (uint32_t)(k_row * 256 + (((cb0 + 2) ^ (k_row & 7)) << 4));
    uint32_t b0, b1, b2, b3, b4, b5, b6, b7;
    ldsm_x4_t(b0, b1, b2, b3, baddr0);
    ldsm_x4_t(b4, b5, b6, b7, baddr1);

    mma16816(d[0][0], d[0][1], d[0][2], d[0][3], a0, a1, a2, a3, b0, b1);
    mma16816(d[1][0], d[1][1], d[1][2], d[1][3], a0, a1, a2, a3, b2, b3);
    mma16816(d[2][0], d[2][1], d[2][2], d[2][3], a0, a1, a2, a3, b4, b5);
    mma16816(d[3][0], d[3][1], d[3][2], d[3][3], a0, a1, a2, a3, b6, b7);
  }
  __syncthreads();

  {
    int crow = wr * 16 + (lane >> 2);
    int ccol0 = wc * 32 + (lane & 3) * 2;
#pragma unroll
    for (int t = 0; t < 4; ++t) {
      int c = ccol0 + t * 8;
      __half2 lo = __floats2half2_rn(d[t][0], d[t][1]);
      __half2 hi = __floats2half2_rn(d[t][2], d[t][3]);
      *(__half2*)(sA + crow * 128 + c) = lo;
      *(__half2*)(sA + (crow + 8) * 128 + c) = hi;
    }
  }
  __syncthreads();

  float4 as = sAs4[lane], ad = sAd4[lane];
  int head = lane >> 3;
#pragma unroll
  for (int m = 0; m < 4; ++m) {
    int r = warp * 4 + m;
    int n = base + r;
    uint2 u = *(uint2*)(sA + r * 128 + lane * 4);
    __half2 p0 = *(__half2*)&u.x;
    __half2 p1 = *(__half2*)&u.y;
    float2 f0 = __half22float2(p0);
    float2 f1 = __half22float2(p1);
    float ts = f0.x * as.x + f0.y * as.y + f1.x * as.z + f1.y * as.w;
    float td = f0.x * ad.x + f0.y * ad.y + f1.x * ad.z + f1.y * ad.w;
    ts += __shfl_xor_sync(0xffffffffu, ts, 1);
    ts += __shfl_xor_sync(0xffffffffu, ts, 2);
    ts += __shfl_xor_sync(0xffffffffu, ts, 4);
    td += __shfl_xor_sync(0xffffffffu, td, 1);
    td += __shfl_xor_sync(0xffffffffu, td, 2);
    td += __shfl_xor_sync(0xffffffffu, td, 4);
    if (n < N) {
      *(uint2*)(g_h2h + (size_t)n * 128 + lane * 4) = u;
      if ((lane & 7) == 0) {
        ((float*)&g_asrc2[n])[head] = ts;
        ((float*)&g_adst2[n])[head] = td;
      }
    }
  }
}

// ---------------- GAT aggregation: warp per dst node, single pass -----------
__device__ __forceinline__ void acc_h4(const __half* __restrict__ hh, int s,
                                       int lane, float al,
                                       float& ax, float& ay, float& az, float& aw) {
  uint2 u = *(const uint2*)(hh + (size_t)s * 128 + lane * 4);
  __half2 p0 = *(__half2*)&u.x;
  __half2 p1 = *(__half2*)&u.y;
  float2 f0 = __half22float2(p0);
  float2 f1 = __half22float2(p1);
  ax = fmaf(f0.x, al, ax);
  ay = fmaf(f0.y, al, ay);
  az = fmaf(f1.x, al, az);
  aw = fmaf(f1.y, al, aw);
}

__global__ void gat_aggregate_kernel(float* __restrict__ dout,
                                     const float* __restrict__ bias,
                                     const float* __restrict__ wlin,
                                     const float* __restrict__ blin,
                                     int N, int mode) {
  int gw = (blockIdx.x * blockDim.x + threadIdx.x) >> 5;
  int lane = threadIdx.x & 31;
  if (gw >= N) return;

  const __half* hh    = (mode == 0) ? g_h1h : g_h2h;
  const float*  asrcf = (const float*)((mode == 0) ? g_asrc1 : g_asrc2);
  const float*  adstf = (const float*)((mode == 0) ? g_adst1 : g_adst2);

  int rs = g_rowptr[gw], re = g_rowptr[gw + 1];
  int head = lane >> 3;  // lane owns channels [4*lane, 4*lane+4)
  float adh = __ldg(&adstf[gw * 4 + head]);

  float ax = 0.f, ay = 0.f, az = 0.f, aw = 0.f, den = 0.f;

  for (int c = rs; c < re; c += 32) {
    int cnt = re - c; if (cnt > 32) cnt = 32;
    int idx = c + lane;
    int sv = g_colsrc[idx < re ? idx : re - 1];  // coalesced prefetch
    int j = 0;
    for (; j + 8 <= cnt; j += 8) {
      int s[8];
#pragma unroll
      for (int u = 0; u < 8; ++u) s[u] = __shfl_sync(0xffffffffu, sv, j + u);
      float av[8];
#pragma unroll
      for (int u = 0; u < 8; ++u) av[u] = __ldg(&asrcf[s[u] * 4 + head]);
      float al[8];
#pragma unroll
      for (int u = 0; u < 8; ++u) al[u] = __expf(lrelu(av[u] + adh));
#pragma unroll
      for (int u = 0; u < 8; ++u) {
        acc_h4(hh, s[u], lane, al[u], ax, ay, az, aw);
        den += al[u];
      }
    }
    for (; j < cnt; ++j) {
      int s0 = __shfl_sync(0xffffffffu, sv, j);
      float al = __expf(lrelu(__ldg(&asrcf[s0 * 4 + head]) + adh));
      acc_h4(hh, s0, lane, al, ax, ay, az, aw);
      den += al;
    }
  }
  float rd = 1.0f / den;  // den identical across each head's 8 lanes
  ax *= rd; ay *= rd; az *= rd; aw *= rd;

  if (mode == 0) {
    float4 b = ((const float4*)bias)[lane];
    __half2 lo = __floats2half2_rn(fmaxf(ax + b.x, 0.f), fmaxf(ay + b.y, 0.f));
    __half2 hi = __floats2half2_rn(fmaxf(az + b.z, 0.f), fmaxf(aw + b.w, 0.f));
    uint2 packed;
    packed.x = *(unsigned*)&lo;
    packed.y = *(unsigned*)&hi;
    *(uint2*)(g_out1h + (size_t)gw * 128 + lane * 4) = packed;  // device symbol
  } else {
    ax += __shfl_xor_sync(0xffffffffu, ax, 8);
    ax += __shfl_xor_sync(0xffffffffu, ax, 16);
    ay += __shfl_xor_sync(0xffffffffu, ay, 8);
    ay += __shfl_xor_sync(0xffffffffu, ay, 16);
    az += __shfl_xor_sync(0xffffffffu, az, 8);
    az += __shfl_xor_sync(0xffffffffu, az, 16);
    aw += __shfl_xor_sync(0xffffffffu, aw, 8);
    aw += __shfl_xor_sync(0xffffffffu, aw, 16);
    int c0 = (lane & 7) * 4;
    float v0 = fmaxf(ax * 0.25f + bias[c0 + 0], 0.f);
    float v1 = fmaxf(ay * 0.25f + bias[c0 + 1], 0.f);
    float v2 = fmaxf(az * 0.25f + bias[c0 + 2], 0.f);
    float v3 = fmaxf(aw * 0.25f + bias[c0 + 3], 0.f);
    float p = v0 * wlin[c0] + v1 * wlin[c0 + 1] + v2 * wlin[c0 + 2] + v3 * wlin[c0 + 3];
    p += __shfl_xor_sync(0xffffffffu, p, 1);
    p += __shfl_xor_sync(0xffffffffu, p, 2);
    p += __shfl_xor_sync(0xffffffffu, p, 4);
    if (lane == 0) dout[gw] = p + blin[0];
  }
}

// ---------------- launch -----------------------------------------------------
extern "C" void kernel_launch(void* const* d_in, const int* in_sizes, int n_in,
                              void* d_out, int out_size) {
  const float* x    = (const float*)d_in[0];
  const int*   ei   = (const int*)d_in[1];
  const float* W1   = (const float*)d_in[2];
  const float* as1  = (const float*)d_in[3];
  const float* ad1  = (const float*)d_in[4];
  const float* b1   = (const float*)d_in[5];
  const float* W2   = (const float*)d_in[6];
  const float* as2  = (const float*)d_in[7];
  const float* ad2  = (const float*)d_in[8];
  const float* b2   = (const float*)d_in[9];
  const float* wlin = (const float*)d_in[10];
  const float* blin = (const float*)d_in[11];

  int N = in_sizes[0] / 8;
  int E = in_sizes[1] / 2;
  const int* srcv = ei;
  const int* dstv = ei + E;
  int ntiles = (N + STILE - 1) / STILE;

  // CSR build (graph identical for both layers), now fully coalesced
  init_count_kernel<<<(N + 4 + 255) / 256, 256>>>(N);
  hist_kernel<<<(E + 255) / 256, 256>>>(dstv, E);
  scanA_kernel<<<ntiles, 1024>>>(N);
  scanB_kernel<<<1, 32>>>(ntiles, N);
  scanC_kernel<<<ntiles, 1024>>>(N);
  scatter_kernel<<<(E + N + 255) / 256, 256>>>(srcv, dstv, E, N);

  // layer 1 (aggregate writes g_out1h internally)
  gemm1_kernel<<<(N + 7) / 8, 128>>>(x, W1, as1, ad1, N);
  gat_aggregate_kernel<<<(N + 7) / 8, 256>>>((float*)d_out, b1, nullptr, nullptr, N, 0);

  // layer 2: tensor-core GEMM + fused epilogues
  gemm2_kernel<<<(N + 31) / 32, 256>>>(W2, as2, ad2, N);
  gat_aggregate_kernel<<<(N + 7) / 8, 256>>>((float*)d_out, b2, wlin, blin, N, 1);
}